// round 2
// baseline (speedup 1.0000x reference)
#include <cuda_runtime.h>
#include <cstdint>
#include <math.h>

// ---------------- problem constants ----------------
#define BATCH 16384
#define ZD 32
#define NE 512
#define GAMMA 0.99f
#define ONE_M_GAMMA 0.01f
#define BETA 1.0f

#define OFF_SCAL (BATCH * 784)   // 12,845,056: x_rec size
// d_out layout: [x_rec (B*784)][quant][commit][perplexity][emb_new (512*32)]

// ---------------- scratch (no allocation allowed) ----------------
__device__ float g_h1[BATCH * 16 * 14 * 14];   // conv1 out / convt1 out
__device__ float g_h2[BATCH * 32 * 7 * 7];     // conv2/res1 out, fc4/res2 out
__device__ float g_a [BATCH * 224];            // fc1 out / fc3 out
__device__ float g_z [BATCH * ZD];             // fc2 out
__device__ int   g_idx[BATCH];
__device__ float g_enorm[NE];
__device__ float g_counts[NE];
__device__ float g_sums[NE * ZD];
__device__ float g_loss[1];

// ======================================================================
// conv1: x[B,1,28,28] -> relu -> h1[B,16,14,14]   (k4 s2 p1)
// 2 images/CTA, 224 thr = 2img x 8ocp x 14oy, padded smem [30][30]
// ======================================================================
__global__ void __launch_bounds__(224) conv1_kernel(
        const float* __restrict__ x,
        const float* __restrict__ w,
        const float* __restrict__ bias,
        float* __restrict__ out) {
    __shared__ float xp[2 * 900];   // [im][30][30], halo of 1
    int b0 = blockIdx.x * 2, t = threadIdx.x;
    for (int i = t; i < 1800; i += 224) xp[i] = 0.f;
    __syncthreads();
    for (int i = t; i < 1568; i += 224) {
        int im = i / 784, j = i % 784;
        int iy = j / 28, ix = j % 28;
        xp[im * 900 + (iy + 1) * 30 + (ix + 1)] = x[(size_t)(b0 + im) * 784 + j];
    }
    __syncthreads();
    int im = t / 112, r = t % 112;
    int ocp = r / 14, oy = r % 14;
    int oc0 = ocp * 2, oc1 = oc0 + 1;
    float acc0[14], acc1[14];
    float b0v = bias[oc0], b1v = bias[oc1];
    #pragma unroll
    for (int j = 0; j < 14; j++) { acc0[j] = b0v; acc1[j] = b1v; }
    const float* base = xp + im * 900;
    #pragma unroll
    for (int ky = 0; ky < 4; ky++) {
        int ry = 2 * oy + ky;          // = (2*oy-1+ky)+1 pad
        float row[30];
        #pragma unroll
        for (int j = 0; j < 30; j++) row[j] = base[ry * 30 + j];
        #pragma unroll
        for (int kx = 0; kx < 4; kx++) {
            float w0 = __ldg(w + oc0 * 16 + ky * 4 + kx);
            float w1 = __ldg(w + oc1 * 16 + ky * 4 + kx);
            #pragma unroll
            for (int ox = 0; ox < 14; ox++) {
                float v = row[2 * ox + kx];
                acc0[ox] += v * w0;
                acc1[ox] += v * w1;
            }
        }
    }
    float* op = out + (size_t)(b0 + im) * 3136 + oy * 14;
    #pragma unroll
    for (int ox = 0; ox < 14; ox++) {
        op[oc0 * 196 + ox] = fmaxf(acc0[ox], 0.f);
        op[oc1 * 196 + ox] = fmaxf(acc1[ox], 0.f);
    }
}

// ======================================================================
// conv2: h1[B,16,14,14] -> h2[B,32,7,7]   (k4 s2 p1, no relu)
// 2 images/CTA, 224 thr = 2img x 16ocp x 7oy, padded smem [16][16][16]
// ======================================================================
__global__ void __launch_bounds__(224) conv2_kernel(
        const float* __restrict__ in,
        const float* __restrict__ w,
        const float* __restrict__ bias,
        float* __restrict__ out) {
    __shared__ float xp[2 * 4096];  // [im][16ic][16][16]
    int b0 = blockIdx.x * 2, t = threadIdx.x;
    for (int i = t; i < 8192; i += 224) xp[i] = 0.f;
    __syncthreads();
    for (int i = t; i < 6272; i += 224) {
        int im = i / 3136, j = i % 3136;
        int ic = j / 196, p = j % 196, iy = p / 14, ix = p % 14;
        xp[im * 4096 + ic * 256 + (iy + 1) * 16 + (ix + 1)] =
            in[(size_t)(b0 + im) * 3136 + j];
    }
    __syncthreads();
    int im = t / 112, r = t % 112;
    int ocp = r / 7, oy = r % 7;
    int oc0 = ocp * 2, oc1 = oc0 + 1;
    float acc0[7], acc1[7];
    float b0v = bias[oc0], b1v = bias[oc1];
    #pragma unroll
    for (int j = 0; j < 7; j++) { acc0[j] = b0v; acc1[j] = b1v; }
    const float* base = xp + im * 4096;
    for (int ic = 0; ic < 16; ic++) {
        const float* xc = base + ic * 256;
        const float* wp0 = w + oc0 * 256 + ic * 16;
        const float* wp1 = w + oc1 * 256 + ic * 16;
        #pragma unroll
        for (int ky = 0; ky < 4; ky++) {
            int ry = 2 * oy + ky;
            float row[16];
            #pragma unroll
            for (int j = 0; j < 16; j++) row[j] = xc[ry * 16 + j];
            #pragma unroll
            for (int kx = 0; kx < 4; kx++) {
                float w0 = __ldg(wp0 + ky * 4 + kx);
                float w1 = __ldg(wp1 + ky * 4 + kx);
                #pragma unroll
                for (int ox = 0; ox < 7; ox++) {
                    float v = row[2 * ox + kx];
                    acc0[ox] += v * w0;
                    acc1[ox] += v * w1;
                }
            }
        }
    }
    float* op = out + (size_t)(b0 + im) * 1568 + oy * 7;
    #pragma unroll
    for (int ox = 0; ox < 7; ox++) {
        op[oc0 * 49 + ox] = acc0[ox];
        op[oc1 * 49 + ox] = acc1[ox];
    }
}

// ======================================================================
// res stack (in-place): y = relu(x + conv1x1(relu(conv3x3(relu(x)))))
// 2 images/CTA, 448 threads.
// phase1: 2img x 32ocp x 7oy, relu'd padded input [32][9][9]
// phase2: 2img x 32oc x 7row, residual re-read from gmem (L1 hit)
// ======================================================================
__global__ void __launch_bounds__(448) res_kernel(
        float* __restrict__ buf,
        const float* __restrict__ pw1,
        const float* __restrict__ pw2) {
    __shared__ float xp[2 * 2592];   // [im][32ic][9][9], relu'd, halo 1
    __shared__ float rb[2 * 3136];   // [im][64oc][49] phase-1 output
    int b0 = blockIdx.x * 2, t = threadIdx.x;
    for (int i = t; i < 5184; i += 448) xp[i] = 0.f;
    __syncthreads();
    for (int i = t; i < 3136; i += 448) {
        int im = i / 1568, j = i % 1568;
        int ic = j / 49, p = j % 49, iy = p / 7, ix = p % 7;
        float v = buf[(size_t)(b0 + im) * 1568 + j];
        xp[im * 2592 + ic * 81 + (iy + 1) * 9 + (ix + 1)] = fmaxf(v, 0.f);
    }
    __syncthreads();

    // phase 1: conv3x3 (32->64), relu output to rb
    {
        int im = t / 224, r = t % 224;
        int ocp = r / 7, oy = r % 7;
        int oc0 = ocp * 2, oc1 = oc0 + 1;
        float acc0[7] = {}, acc1[7] = {};
        const float* base = xp + im * 2592;
        for (int ic = 0; ic < 32; ic++) {
            const float* xc = base + ic * 81;
            const float* wp0 = pw1 + oc0 * 288 + ic * 9;
            const float* wp1 = pw1 + oc1 * 288 + ic * 9;
            #pragma unroll
            for (int ky = 0; ky < 3; ky++) {
                float row[9];
                #pragma unroll
                for (int j = 0; j < 9; j++) row[j] = xc[(oy + ky) * 9 + j];
                #pragma unroll
                for (int kx = 0; kx < 3; kx++) {
                    float w0 = __ldg(wp0 + ky * 3 + kx);
                    float w1 = __ldg(wp1 + ky * 3 + kx);
                    #pragma unroll
                    for (int ox = 0; ox < 7; ox++) {
                        float v = row[ox + kx];
                        acc0[ox] += v * w0;
                        acc1[ox] += v * w1;
                    }
                }
            }
        }
        float* rp = rb + im * 3136 + oy * 7;
        #pragma unroll
        for (int ox = 0; ox < 7; ox++) {
            rp[oc0 * 49 + ox] = fmaxf(acc0[ox], 0.f);
            rp[oc1 * 49 + ox] = fmaxf(acc1[ox], 0.f);
        }
    }
    __syncthreads();

    // phase 2: conv1x1 (64->32) + residual + relu
    {
        int im = t / 224, r = t % 224;
        int oc = r / 7, sg = r % 7;
        float acc[7] = {};
        const float* rbase = rb + im * 3136 + sg * 7;
        const float* w2p = pw2 + oc * 64;
        for (int ic = 0; ic < 64; ic++) {
            float wv = __ldg(w2p + ic);
            const float* rp = rbase + ic * 49;
            #pragma unroll
            for (int j = 0; j < 7; j++) acc[j] += rp[j] * wv;
        }
        float* bp = buf + (size_t)(b0 + im) * 1568 + oc * 49 + sg * 7;
        #pragma unroll
        for (int j = 0; j < 7; j++)
            bp[j] = fmaxf(bp[j] + acc[j], 0.f);
    }
}

// ======================================================================
// tiled GEMM: C[M,N] = A[M,K] @ W[N,K]^T + bias, optional relu
// BM=64 BN=64 BK=16, 256 threads, 4x4 micro-tile. M%64==0, K%16==0.
// ======================================================================
template<int RELU>
__global__ void gemm_nt(const float* __restrict__ A,
                        const float* __restrict__ W,
                        const float* __restrict__ bias,
                        float* __restrict__ C,
                        int M, int N, int K) {
    __shared__ float As[16][68];
    __shared__ float Ws[16][68];
    int t = threadIdx.x;
    int tx = t % 16, ty = t / 16;
    int m0 = blockIdx.x * 64, n0 = blockIdx.y * 64;
    int lr = t / 4;            // 0..63
    int lc = (t % 4) * 4;      // 0,4,8,12
    float c[4][4] = {};
    for (int k0 = 0; k0 < K; k0 += 16) {
        float4 av = *(const float4*)(A + (size_t)(m0 + lr) * K + k0 + lc);
        As[lc + 0][lr] = av.x; As[lc + 1][lr] = av.y;
        As[lc + 2][lr] = av.z; As[lc + 3][lr] = av.w;
        int wn = n0 + lr;
        float4 wv = make_float4(0.f, 0.f, 0.f, 0.f);
        if (wn < N) wv = *(const float4*)(W + (size_t)wn * K + k0 + lc);
        Ws[lc + 0][lr] = wv.x; Ws[lc + 1][lr] = wv.y;
        Ws[lc + 2][lr] = wv.z; Ws[lc + 3][lr] = wv.w;
        __syncthreads();
        #pragma unroll
        for (int kk = 0; kk < 16; kk++) {
            float a[4], wq[4];
            #pragma unroll
            for (int i = 0; i < 4; i++) a[i] = As[kk][ty * 4 + i];
            #pragma unroll
            for (int j = 0; j < 4; j++) wq[j] = Ws[kk][tx * 4 + j];
            #pragma unroll
            for (int i = 0; i < 4; i++)
                #pragma unroll
                for (int j = 0; j < 4; j++) c[i][j] += a[i] * wq[j];
        }
        __syncthreads();
    }
    #pragma unroll
    for (int i = 0; i < 4; i++) {
        int m = m0 + ty * 4 + i;
        #pragma unroll
        for (int j = 0; j < 4; j++) {
            int n = n0 + tx * 4 + j;
            if (n < N) {
                float v = c[i][j] + bias[n];
                if (RELU) v = fmaxf(v, 0.f);
                C[(size_t)m * N + n] = v;
            }
        }
    }
}

// ======================================================================
// fc2: z[B,32] = A[B,224] @ w[32,224]^T + b   (no relu)
// ======================================================================
__global__ void fc2_kernel(const float* __restrict__ A,
                           const float* __restrict__ w,
                           const float* __restrict__ bias,
                           float* __restrict__ out) {
    __shared__ float ws[32 * 224];
    int t = threadIdx.x;   // 256
    for (int i = t; i < 7168; i += 256) ws[i] = w[i];
    __syncthreads();
    int n = t & 31, r = t >> 5;
    int b = blockIdx.x * 8 + r;
    const float* ap = A + (size_t)b * 224;
    const float* wp = ws + n * 224;
    float acc = bias[n];
    #pragma unroll 8
    for (int k = 0; k < 224; k++) acc += ap[k] * wp[k];
    out[(size_t)b * 32 + n] = acc;
}

// ======================================================================
// VQ helpers
// ======================================================================
__global__ void enorm_kernel(const float* __restrict__ emb, float* __restrict__ enorm) {
    int e = blockIdx.x * blockDim.x + threadIdx.x;
    if (e < NE) {
        float s = 0.f;
        #pragma unroll
        for (int d = 0; d < ZD; d++) { float v = emb[e * ZD + d]; s += v * v; }
        enorm[e] = s;
    }
}

__global__ void zero_kernel(float* __restrict__ counts, float* __restrict__ sums,
                            float* __restrict__ loss) {
    int i = blockIdx.x * blockDim.x + threadIdx.x;
    if (i < NE) counts[i] = 0.f;
    if (i < NE * ZD) sums[i] = 0.f;
    if (i == 0) loss[0] = 0.f;
}

// one warp per row: argmin over 512 codes (first-min tie-break), then
// counts/sums/loss accumulation via atomics
__global__ void vq_kernel(const float* __restrict__ z,
                          const float* __restrict__ emb,
                          const float* __restrict__ enorm,
                          int* __restrict__ idx,
                          float* __restrict__ counts,
                          float* __restrict__ sums,
                          float* __restrict__ loss) {
    int gw = (blockIdx.x * blockDim.x + threadIdx.x) >> 5;  // row
    int lane = threadIdx.x & 31;
    int wl = threadIdx.x >> 5;
    __shared__ float zs[8][ZD];
    if (gw >= BATCH) return;
    zs[wl][lane] = z[(size_t)gw * ZD + lane];
    __syncwarp();
    float best = 3.4e38f; int bi = NE;
    for (int e = lane; e < NE; e += 32) {
        const float* ep = emb + e * ZD;
        float dot = 0.f;
        #pragma unroll
        for (int d = 0; d < ZD; d++) dot += zs[wl][d] * __ldg(ep + d);
        float s = enorm[e] - 2.f * dot;
        if (s < best) { best = s; bi = e; }
    }
    #pragma unroll
    for (int off = 16; off; off >>= 1) {
        float ob = __shfl_xor_sync(0xffffffffu, best, off);
        int   oi = __shfl_xor_sync(0xffffffffu, bi, off);
        if (ob < best || (ob == best && oi < bi)) { best = ob; bi = oi; }
    }
    float zl = zs[wl][lane];
    float diff = __ldg(emb + (size_t)bi * ZD + lane) - zl;
    float d2 = diff * diff;
    #pragma unroll
    for (int off = 16; off; off >>= 1) d2 += __shfl_xor_sync(0xffffffffu, d2, off);
    if (lane == 0) {
        idx[gw] = bi;
        atomicAdd(&counts[bi], 1.f);
        atomicAdd(loss, d2);
    }
    atomicAdd(&sums[bi * ZD + lane], zl);
}

__global__ void embnew_kernel(const float* __restrict__ m_mat,
                              const float* __restrict__ n_mat,
                              const float* __restrict__ sums,
                              const float* __restrict__ counts,
                              float* __restrict__ out) {
    int i = blockIdx.x * blockDim.x + threadIdx.x;
    if (i < NE * ZD) {
        int e = i >> 5;
        float m = m_mat[i] * GAMMA + sums[i] * ONE_M_GAMMA;
        float n = n_mat[e] * GAMMA + counts[e] * ONE_M_GAMMA;
        out[i] = m / n;
    }
}

__global__ void finalize_kernel(const float* __restrict__ counts,
                                const float* __restrict__ loss,
                                float* __restrict__ out_scalars) {
    __shared__ float red[NE];
    int t = threadIdx.x;   // 512
    float c = counts[t];
    float em = c * (1.f / (float)BATCH);
    red[t] = em * logf(em + 1e-10f);
    __syncthreads();
    for (int s = 256; s; s >>= 1) {
        if (t < s) red[t] += red[t + s];
        __syncthreads();
    }
    if (t == 0) {
        float q = loss[0] * (1.f / ((float)BATCH * (float)ZD));
        out_scalars[0] = q;          // quant_loss
        out_scalars[1] = BETA * q;   // commit_loss
        out_scalars[2] = expf(-red[0]);
    }
}

// ======================================================================
// fc3: out[b,n] = relu(b[n] + sum_k emb[idx[b],k] * w[n,k])   (K=32,N=224)
// ======================================================================
__global__ void fc3_kernel(const float* __restrict__ emb,
                           const int* __restrict__ idx,
                           const float* __restrict__ w,
                           const float* __restrict__ bias,
                           float* __restrict__ out) {
    __shared__ float zq[ZD];
    int b = blockIdx.x, t = threadIdx.x;   // 224
    if (t < ZD) zq[t] = emb[(size_t)idx[b] * ZD + t];
    __syncthreads();
    const float* wp = w + t * ZD;
    float acc = bias[t];
    #pragma unroll
    for (int k = 0; k < ZD; k++) acc += zq[k] * __ldg(wp + k);
    out[(size_t)b * 224 + t] = fmaxf(acc, 0.f);
}

// ======================================================================
// convt1: in[B,32,7,7] -> relu -> out[B,16,14,14]   (k4 s2 p1)
// w[32,16,4,4]. 2 images/CTA, 224 thr = 2img x 8ocp x 14oy,
// padded smem [32][9][9]; stride parity resolved at compile time.
// ======================================================================
__global__ void __launch_bounds__(224) convt1_kernel(
        const float* __restrict__ in,
        const float* __restrict__ w,
        const float* __restrict__ bias,
        float* __restrict__ out) {
    __shared__ float xp[2 * 2592];   // [im][32ic][9][9], halo 1
    int b0 = blockIdx.x * 2, t = threadIdx.x;
    for (int i = t; i < 5184; i += 224) xp[i] = 0.f;
    __syncthreads();
    for (int i = t; i < 3136; i += 224) {
        int im = i / 1568, j = i % 1568;
        int ic = j / 49, p = j % 49, iy = p / 7, ix = p % 7;
        xp[im * 2592 + ic * 81 + (iy + 1) * 9 + (ix + 1)] =
            in[(size_t)(b0 + im) * 1568 + j];
    }
    __syncthreads();
    int im = t / 112, r = t % 112;
    int ocp = r / 14, oy = r % 14;
    int oc0 = ocp * 2, oc1 = oc0 + 1;
    float acc0[14], acc1[14];
    float b0v = bias[oc0], b1v = bias[oc1];
    #pragma unroll
    for (int j = 0; j < 14; j++) { acc0[j] = b0v; acc1[j] = b1v; }
    const float* base = xp + im * 2592;
    for (int ic = 0; ic < 32; ic++) {
        const float* xc = base + ic * 81;
        const float* wp0 = w + ic * 256 + oc0 * 16;
        const float* wp1 = w + ic * 256 + oc1 * 16;
        #pragma unroll
        for (int ky = 0; ky < 4; ky++) {
            int ty = oy + 1 - ky;
            if (ty & 1) continue;            // runtime parity: 2 of 4 taken
            int iy = ty >> 1;                // -1..7 (arith shift ok)
            float row[9];
            #pragma unroll
            for (int j = 0; j < 9; j++) row[j] = xc[(iy + 1) * 9 + j];
            #pragma unroll
            for (int kx = 0; kx < 4; kx++) {
                float w0 = __ldg(wp0 + ky * 4 + kx);
                float w1 = __ldg(wp1 + ky * 4 + kx);
                #pragma unroll
                for (int ox = 0; ox < 14; ox++) {
                    int s = ox + 1 - kx;             // compile-time
                    if ((s & 1) == 0) {
                        float v = row[s / 2 + 1];    // s/2 in -1..7
                        acc0[ox] += v * w0;
                        acc1[ox] += v * w1;
                    }
                }
            }
        }
    }
    float* op = out + (size_t)(b0 + im) * 3136 + oy * 14;
    #pragma unroll
    for (int ox = 0; ox < 14; ox++) {
        op[oc0 * 196 + ox] = fmaxf(acc0[ox], 0.f);
        op[oc1 * 196 + ox] = fmaxf(acc1[ox], 0.f);
    }
}

// ======================================================================
// convt2: in[B,16,14,14] -> out[B,1,28,28]  (k4 s2 p1, no relu) -> d_out
// 2 images/CTA, 112 thr = 2img x 28oy x 2half, padded smem [16][16][16]
// ======================================================================
__global__ void __launch_bounds__(112) convt2_kernel(
        const float* __restrict__ in,
        const float* __restrict__ w,
        const float* __restrict__ bias,
        float* __restrict__ out) {
    __shared__ float xp[2 * 4096];   // [im][16ic][16][16], halo 1
    int b0 = blockIdx.x * 2, t = threadIdx.x;
    for (int i = t; i < 8192; i += 112) xp[i] = 0.f;
    __syncthreads();
    for (int i = t; i < 6272; i += 112) {
        int im = i / 3136, j = i % 3136;
        int ic = j / 196, p = j % 196, iy = p / 14, ix = p % 14;
        xp[im * 4096 + ic * 256 + (iy + 1) * 16 + (ix + 1)] =
            in[(size_t)(b0 + im) * 3136 + j];
    }
    __syncthreads();
    int im = t / 56, r = t % 56;
    int oy = r / 2, h = r % 2;       // ox in [14h, 14h+13]
    float acc[14];
    float bv = bias[0];
    #pragma unroll
    for (int j = 0; j < 14; j++) acc[j] = bv;
    const float* base = xp + im * 4096;
    for (int ic = 0; ic < 16; ic++) {
        const float* xc = base + ic * 256;
        const float* wp = w + ic * 16;
        #pragma unroll
        for (int ky = 0; ky < 4; ky++) {
            int ty = oy + 1 - ky;
            if (ty & 1) continue;
            int iy = ty >> 1;                 // -1..14
            float row[9];
            #pragma unroll
            for (int j = 0; j < 9; j++) row[j] = xc[(iy + 1) * 16 + 7 * h + j];
            #pragma unroll
            for (int kx = 0; kx < 4; kx++) {
                float wv = __ldg(wp + ky * 4 + kx);
                #pragma unroll
                for (int jj = 0; jj < 14; jj++) {
                    int s = jj + 1 - kx;              // compile-time
                    if ((s & 1) == 0)
                        acc[jj] += row[s / 2 + 1] * wv;
                }
            }
        }
    }
    float* op = out + (size_t)(b0 + im) * 784 + oy * 28 + 14 * h;
    #pragma unroll
    for (int j = 0; j < 14; j++) op[j] = acc[j];
}

// ======================================================================
// launch
// ======================================================================
extern "C" void kernel_launch(void* const* d_in, const int* in_sizes, int n_in,
                              void* d_out, int out_size) {
    const float* x        = (const float*)d_in[0];
    const float* conv1_w  = (const float*)d_in[1];
    const float* conv1_b  = (const float*)d_in[2];
    const float* conv2_w  = (const float*)d_in[3];
    const float* conv2_b  = (const float*)d_in[4];
    const float* res1_w1  = (const float*)d_in[5];
    const float* res1_w2  = (const float*)d_in[6];
    const float* fc1_w    = (const float*)d_in[7];
    const float* fc1_b    = (const float*)d_in[8];
    const float* fc2_w    = (const float*)d_in[9];
    const float* fc2_b    = (const float*)d_in[10];
    const float* emb      = (const float*)d_in[11];
    const float* n_mat    = (const float*)d_in[12];
    const float* m_mat    = (const float*)d_in[13];
    const float* fc3_w    = (const float*)d_in[14];
    const float* fc3_b    = (const float*)d_in[15];
    const float* fc4_w    = (const float*)d_in[16];
    const float* fc4_b    = (const float*)d_in[17];
    const float* res2_w1  = (const float*)d_in[18];
    const float* res2_w2  = (const float*)d_in[19];
    const float* convt1_w = (const float*)d_in[20];
    const float* convt1_b = (const float*)d_in[21];
    const float* convt2_w = (const float*)d_in[22];
    const float* convt2_b = (const float*)d_in[23];
    float* out = (float*)d_out;

    float *h1, *h2, *a, *z, *enorm, *counts, *sums, *loss;
    int* idx;
    cudaGetSymbolAddress((void**)&h1,     g_h1);
    cudaGetSymbolAddress((void**)&h2,     g_h2);
    cudaGetSymbolAddress((void**)&a,      g_a);
    cudaGetSymbolAddress((void**)&z,      g_z);
    cudaGetSymbolAddress((void**)&idx,    g_idx);
    cudaGetSymbolAddress((void**)&enorm,  g_enorm);
    cudaGetSymbolAddress((void**)&counts, g_counts);
    cudaGetSymbolAddress((void**)&sums,   g_sums);
    cudaGetSymbolAddress((void**)&loss,   g_loss);

    // encoder
    conv1_kernel<<<BATCH / 2, 224>>>(x, conv1_w, conv1_b, h1);
    conv2_kernel<<<BATCH / 2, 224>>>(h1, conv2_w, conv2_b, h2);
    res_kernel  <<<BATCH / 2, 448>>>(h2, res1_w1, res1_w2);
    gemm_nt<1><<<dim3(BATCH / 64, (224 + 63) / 64), 256>>>(h2, fc1_w, fc1_b, a,
                                                           BATCH, 224, 1568);
    fc2_kernel<<<BATCH / 8, 256>>>(a, fc2_w, fc2_b, z);

    // VQ
    zero_kernel <<<(NE * ZD + 255) / 256, 256>>>(counts, sums, loss);
    enorm_kernel<<<2, 256>>>(emb, enorm);
    vq_kernel   <<<BATCH / 8, 256>>>(z, emb, enorm, idx, counts, sums, loss);
    embnew_kernel  <<<(NE * ZD + 255) / 256, 256>>>(m_mat, n_mat, sums, counts,
                                                    out + OFF_SCAL + 3);
    finalize_kernel<<<1, NE>>>(counts, loss, out + OFF_SCAL);

    // decoder
    fc3_kernel<<<BATCH, 224>>>(emb, idx, fc3_w, fc3_b, a);
    gemm_nt<1><<<dim3(BATCH / 64, (1568 + 63) / 64), 256>>>(a, fc4_w, fc4_b, h2,
                                                            BATCH, 1568, 224);
    res_kernel   <<<BATCH / 2, 448>>>(h2, res2_w1, res2_w2);
    convt1_kernel<<<BATCH / 2, 224>>>(h2, convt1_w, convt1_b, h1);
    convt2_kernel<<<BATCH / 2, 112>>>(h1, convt2_w, convt2_b, out);
}

// round 3
// speedup vs baseline: 1.2362x; 1.2362x over previous
#include <cuda_runtime.h>
#include <cstdint>
#include <math.h>

// ---------------- problem constants ----------------
#define BATCH 16384
#define ZD 32
#define NE 512
#define GAMMA 0.99f
#define ONE_M_GAMMA 0.01f
#define BETA 1.0f

#define OFF_SCAL (BATCH * 784)   // 12,845,056: x_rec size
// d_out layout: [x_rec (B*784)][quant][commit][perplexity][emb_new (512*32)]

// ---------------- scratch (no allocation allowed) ----------------
__device__ float g_h1[BATCH * 16 * 14 * 14];   // conv1 out / convt1 out
__device__ float g_h2[BATCH * 32 * 7 * 7];     // conv2/res1 out, fc4/res2 out
__device__ float g_a [BATCH * 224];            // fc1 out / fc3 out
__device__ float g_z [BATCH * ZD];             // fc2 out
__device__ int   g_idx[BATCH];
__device__ float g_enorm[NE];
__device__ float g_counts[NE];
__device__ float g_sums[NE * ZD];
__device__ float g_loss[1];

// ---------------- tf32 mma helpers ----------------
__device__ __forceinline__ float to_tf32(float x) {
    float y;
    asm("cvt.rna.tf32.f32 %0, %1;" : "=f"(y) : "f"(x));
    return y;
}

__device__ __forceinline__ void mma_tf32(float* d, const unsigned* a,
                                         unsigned b0, unsigned b1) {
    asm volatile(
        "mma.sync.aligned.m16n8k8.row.col.f32.tf32.tf32.f32 "
        "{%0,%1,%2,%3}, {%4,%5,%6,%7}, {%8,%9}, {%0,%1,%2,%3};\n"
        : "+f"(d[0]), "+f"(d[1]), "+f"(d[2]), "+f"(d[3])
        : "r"(a[0]), "r"(a[1]), "r"(a[2]), "r"(a[3]), "r"(b0), "r"(b1));
}

// ======================================================================
// conv1: x[B,1,28,28] -> relu -> h1[B,16,14,14]   (k4 s2 p1)   [round-1]
// ======================================================================
__global__ void conv1_kernel(const float* __restrict__ x,
                             const float* __restrict__ w,
                             const float* __restrict__ bias,
                             float* __restrict__ out) {
    __shared__ float img[784];
    __shared__ float ws[256];
    int b = blockIdx.x, t = threadIdx.x;
    const float* ip = x + (size_t)b * 784;
    for (int i = t; i < 784; i += 256) img[i] = ip[i];
    if (t < 256) ws[t] = w[t];
    __syncthreads();
    float* op = out + (size_t)b * 3136;
    for (int o = t; o < 3136; o += 256) {
        int oc = o / 196, s = o % 196, oy = s / 14, ox = s % 14;
        float acc = bias[oc];
        const float* wp = ws + oc * 16;
        #pragma unroll
        for (int ky = 0; ky < 4; ky++) {
            int iy = 2 * oy - 1 + ky;
            if ((unsigned)iy < 28u) {
                #pragma unroll
                for (int kx = 0; kx < 4; kx++) {
                    int ix = 2 * ox - 1 + kx;
                    if ((unsigned)ix < 28u)
                        acc += img[iy * 28 + ix] * wp[ky * 4 + kx];
                }
            }
        }
        op[o] = fmaxf(acc, 0.f);
    }
}

// ======================================================================
// conv2: h1[B,16,14,14] -> h2[B,32,7,7]   (k4 s2 p1, no relu)  [round-1]
// ======================================================================
__global__ void conv2_kernel(const float* __restrict__ in,
                             const float* __restrict__ w,
                             const float* __restrict__ bias,
                             float* __restrict__ out) {
    __shared__ float img[16 * 196];
    int b = blockIdx.x, t = threadIdx.x;   // 224 threads
    const float* ip = in + (size_t)b * 3136;
    for (int i = t; i < 3136; i += 224) img[i] = ip[i];
    __syncthreads();
    int oc = t / 7, oy = t % 7;
    float acc[7];
    float bv = bias[oc];
    #pragma unroll
    for (int j = 0; j < 7; j++) acc[j] = bv;
    for (int ic = 0; ic < 16; ic++) {
        const float* xc = img + ic * 196;
        const float* wp = w + oc * 256 + ic * 16;
        #pragma unroll
        for (int ky = 0; ky < 4; ky++) {
            int iy = 2 * oy - 1 + ky;
            if (iy < 0 || iy >= 14) continue;
            float row[14];
            #pragma unroll
            for (int j = 0; j < 14; j++) row[j] = xc[iy * 14 + j];
            #pragma unroll
            for (int kx = 0; kx < 4; kx++) {
                float wv = __ldg(wp + ky * 4 + kx);
                #pragma unroll
                for (int ox = 0; ox < 7; ox++) {
                    int ix = 2 * ox - 1 + kx;
                    if (ix >= 0 && ix < 14) acc[ox] += row[ix] * wv;
                }
            }
        }
    }
    float* op = out + (size_t)b * 1568 + oc * 49 + oy * 7;
    #pragma unroll
    for (int ox = 0; ox < 7; ox++) op[ox] = acc[ox];
}

// ======================================================================
// res stack fp32 (encoder, in-place)                          [round-1]
// ======================================================================
__global__ void res_kernel(float* __restrict__ buf,
                           const float* __restrict__ pw1,
                           const float* __restrict__ pw2) {
    __shared__ float xin[1568];
    __shared__ float r[64 * 49];
    __shared__ float w2s[2048];
    int b = blockIdx.x, t = threadIdx.x;   // 448 threads
    float* bp = buf + (size_t)b * 1568;
    for (int i = t; i < 1568; i += 448) xin[i] = bp[i];
    for (int i = t; i < 2048; i += 448) w2s[i] = pw2[i];
    __syncthreads();
    {
        int oc = t / 7, oy = t % 7;
        float acc[7] = {0.f, 0.f, 0.f, 0.f, 0.f, 0.f, 0.f};
        for (int ic = 0; ic < 32; ic++) {
            const float* xc = xin + ic * 49;
            float row[3][9];
            #pragma unroll
            for (int ky = 0; ky < 3; ky++) {
                int iy = oy - 1 + ky;
                #pragma unroll
                for (int j = 0; j < 9; j++) {
                    int ix = j - 1;
                    row[ky][j] = ((unsigned)iy < 7u && (unsigned)ix < 7u)
                                 ? fmaxf(xc[iy * 7 + ix], 0.f) : 0.f;
                }
            }
            const float* wp = pw1 + oc * 288 + ic * 9;
            #pragma unroll
            for (int ky = 0; ky < 3; ky++)
                #pragma unroll
                for (int kx = 0; kx < 3; kx++) {
                    float wv = __ldg(wp + ky * 3 + kx);
                    #pragma unroll
                    for (int ox = 0; ox < 7; ox++)
                        acc[ox] += row[ky][ox + kx] * wv;
                }
        }
        int base = oc * 49 + oy * 7;
        #pragma unroll
        for (int ox = 0; ox < 7; ox++) r[base + ox] = fmaxf(acc[ox], 0.f);
    }
    __syncthreads();
    if (t < 224) {
        int oc = t / 7, sg = t % 7;
        float acc[7] = {0.f, 0.f, 0.f, 0.f, 0.f, 0.f, 0.f};
        const float* w2p = w2s + oc * 64;
        for (int ic = 0; ic < 64; ic++) {
            float wv = w2p[ic];
            const float* rp = r + ic * 49 + sg * 7;
            #pragma unroll
            for (int j = 0; j < 7; j++) acc[j] += rp[j] * wv;
        }
        int base = oc * 49 + sg * 7;
        #pragma unroll
        for (int j = 0; j < 7; j++)
            bp[base + j] = fmaxf(xin[base + j] + acc[j], 0.f);
    }
}

// ======================================================================
// res stack TF32 tensor-core (decoder use: x >= 0)
// 4 images/CTA, 256 threads (8 warps). M=256 rows (64/img, 49 real).
// Phase1: C1[256,64] = sum over 9 shifts A_s[256,32] @ W1_s[32,64]
// Phase2: C2[256,32] = relu(C1)[256,64] @ W2[64,32]; +residual, relu.
// Input staged as zero-haloed [img][9*9][33]; shifts are constant smem
// offsets, so the mainloop is pure LDS + HMMA.
// ======================================================================
#define RTC_IMSZ  2673                       // 81*33
#define RTC_ZOFF  (4 * RTC_IMSZ)             // zero row for padded rows
#define RTC_XIN   (RTC_ZOFF + 704)           // 11396
#define RTC_W1OFF RTC_XIN
#define RTC_W1SZ  (9 * 32 * 68)              // 19584
#define RTC_W2OFF (RTC_W1OFF + RTC_W1SZ)
#define RTC_W2SZ  (64 * 33)                  // 2112
#define RTC_RSOFF (RTC_W2OFF + RTC_W2SZ)
#define RTC_RSSZ  (256 * 65)                 // 16640
#define RTC_SMEMB ((RTC_RSOFF + RTC_RSSZ) * 4)   // 198,928 bytes

__global__ void __launch_bounds__(256) res_tc_kernel(
        float* __restrict__ buf,
        const float* __restrict__ pw1,
        const float* __restrict__ pw2) {
    extern __shared__ float sm[];
    float* xin = sm;
    float* w1s = sm + RTC_W1OFF;
    float* w2s = sm + RTC_W2OFF;
    float* rs  = sm + RTC_RSOFF;
    int t = threadIdx.x;
    int b0 = blockIdx.x * 4;

    for (int i = t; i < RTC_XIN; i += 256) xin[i] = 0.f;
    for (int i = t; i < 64 * 32 * 9; i += 256) {
        int oc = i / 288, rr = i % 288, ic = rr / 9, s = rr % 9;
        w1s[s * 2176 + ic * 68 + oc] = to_tf32(pw1[i]);
    }
    for (int i = t; i < 2048; i += 256) {
        int oc = i >> 6, ic = i & 63;
        w2s[ic * 33 + oc] = to_tf32(pw2[i]);
    }
    __syncthreads();
    for (int i = t; i < 4 * 1568; i += 256) {
        int img = i / 1568, j = i % 1568;
        int ch = j / 49, p = j % 49, py = p / 7, px = p % 7;
        float v = buf[(size_t)(b0 + img) * 1568 + j];
        xin[img * RTC_IMSZ + ((py + 1) * 9 + (px + 1)) * 33 + ch] =
            to_tf32(fmaxf(v, 0.f));
    }
    __syncthreads();

    int lane = t & 31, w = t >> 5;
    int grp = lane >> 2, tig = lane & 3;
    int wm = w * 32;

    int rb[2][2];
    #pragma unroll
    for (int mi = 0; mi < 2; mi++)
        #pragma unroll
        for (int h = 0; h < 2; h++) {
            int r = wm + mi * 16 + grp + h * 8;
            int img = r >> 6, p = r & 63;
            rb[mi][h] = (p < 49)
                ? img * RTC_IMSZ + ((p / 7) * 9 + (p % 7)) * 33
                : RTC_ZOFF;
        }

    // ---- phase 1 ----
    float acc[2][8][4];
    #pragma unroll
    for (int mi = 0; mi < 2; mi++)
        #pragma unroll
        for (int ni = 0; ni < 8; ni++)
            #pragma unroll
            for (int c = 0; c < 4; c++) acc[mi][ni][c] = 0.f;

    #pragma unroll
    for (int ky = 0; ky < 3; ky++) {
        #pragma unroll
        for (int kx = 0; kx < 3; kx++) {
            int soff = (ky * 9 + kx) * 33;
            const float* wb = w1s + (ky * 3 + kx) * 2176;
            #pragma unroll
            for (int kk = 0; kk < 4; kk++) {
                int kb = kk * 8;
                unsigned a[2][4];
                #pragma unroll
                for (int mi = 0; mi < 2; mi++) {
                    a[mi][0] = __float_as_uint(xin[rb[mi][0] + soff + kb + tig]);
                    a[mi][1] = __float_as_uint(xin[rb[mi][1] + soff + kb + tig]);
                    a[mi][2] = __float_as_uint(xin[rb[mi][0] + soff + kb + tig + 4]);
                    a[mi][3] = __float_as_uint(xin[rb[mi][1] + soff + kb + tig + 4]);
                }
                #pragma unroll
                for (int ni = 0; ni < 8; ni++) {
                    unsigned bb0 = __float_as_uint(wb[(kb + tig) * 68 + ni * 8 + grp]);
                    unsigned bb1 = __float_as_uint(wb[(kb + tig + 4) * 68 + ni * 8 + grp]);
                    mma_tf32(acc[0][ni], a[0], bb0, bb1);
                    mma_tf32(acc[1][ni], a[1], bb0, bb1);
                }
            }
        }
    }

    // relu -> rs (each warp owns its 32 rows end-to-end; no block sync)
    #pragma unroll
    for (int mi = 0; mi < 2; mi++) {
        int rlo = wm + mi * 16 + grp, rhi = rlo + 8;
        #pragma unroll
        for (int ni = 0; ni < 8; ni++) {
            int c0 = ni * 8 + tig * 2;
            rs[rlo * 65 + c0]     = to_tf32(fmaxf(acc[mi][ni][0], 0.f));
            rs[rlo * 65 + c0 + 1] = to_tf32(fmaxf(acc[mi][ni][1], 0.f));
            rs[rhi * 65 + c0]     = to_tf32(fmaxf(acc[mi][ni][2], 0.f));
            rs[rhi * 65 + c0 + 1] = to_tf32(fmaxf(acc[mi][ni][3], 0.f));
        }
    }
    __syncwarp();

    // ---- phase 2 ----
    float acc2[2][4][4];
    #pragma unroll
    for (int mi = 0; mi < 2; mi++)
        #pragma unroll
        for (int ni = 0; ni < 4; ni++)
            #pragma unroll
            for (int c = 0; c < 4; c++) acc2[mi][ni][c] = 0.f;

    #pragma unroll
    for (int kk = 0; kk < 8; kk++) {
        int kb = kk * 8;
        unsigned a[2][4];
        #pragma unroll
        for (int mi = 0; mi < 2; mi++) {
            int rlo = wm + mi * 16 + grp;
            a[mi][0] = __float_as_uint(rs[rlo * 65 + kb + tig]);
            a[mi][1] = __float_as_uint(rs[(rlo + 8) * 65 + kb + tig]);
            a[mi][2] = __float_as_uint(rs[rlo * 65 + kb + tig + 4]);
            a[mi][3] = __float_as_uint(rs[(rlo + 8) * 65 + kb + tig + 4]);
        }
        #pragma unroll
        for (int ni = 0; ni < 4; ni++) {
            unsigned bb0 = __float_as_uint(w2s[(kb + tig) * 33 + ni * 8 + grp]);
            unsigned bb1 = __float_as_uint(w2s[(kb + tig + 4) * 33 + ni * 8 + grp]);
            mma_tf32(acc2[0][ni], a[0], bb0, bb1);
            mma_tf32(acc2[1][ni], a[1], bb0, bb1);
        }
    }

    // epilogue: +residual (exact fp32 from gmem), relu, store
    #pragma unroll
    for (int mi = 0; mi < 2; mi++) {
        int rlo = wm + mi * 16 + grp;
        #pragma unroll
        for (int ni = 0; ni < 4; ni++) {
            #pragma unroll
            for (int ci = 0; ci < 4; ci++) {
                int r = rlo + ((ci >= 2) ? 8 : 0);
                int img = r >> 6, p = r & 63;
                if (p < 49) {
                    int ch = ni * 8 + tig * 2 + (ci & 1);
                    size_t g = (size_t)(b0 + img) * 1568 + ch * 49 + p;
                    float v = acc2[mi][ni][ci] + __ldg(buf + g);
                    buf[g] = fmaxf(v, 0.f);
                }
            }
        }
    }
}

// ======================================================================
// fp32 tiled GEMM (encoder fc1): C = A @ W^T + bias, relu     [round-1]
// ======================================================================
template<int RELU>
__global__ void gemm_nt(const float* __restrict__ A,
                        const float* __restrict__ W,
                        const float* __restrict__ bias,
                        float* __restrict__ C,
                        int M, int N, int K) {
    __shared__ float As[16][68];
    __shared__ float Ws[16][68];
    int t = threadIdx.x;
    int tx = t % 16, ty = t / 16;
    int m0 = blockIdx.x * 64, n0 = blockIdx.y * 64;
    int lr = t / 4;
    int lc = (t % 4) * 4;
    float c[4][4] = {};
    for (int k0 = 0; k0 < K; k0 += 16) {
        float4 av = *(const float4*)(A + (size_t)(m0 + lr) * K + k0 + lc);
        As[lc + 0][lr] = av.x; As[lc + 1][lr] = av.y;
        As[lc + 2][lr] = av.z; As[lc + 3][lr] = av.w;
        int wn = n0 + lr;
        float4 wv = make_float4(0.f, 0.f, 0.f, 0.f);
        if (wn < N) wv = *(const float4*)(W + (size_t)wn * K + k0 + lc);
        Ws[lc + 0][lr] = wv.x; Ws[lc + 1][lr] = wv.y;
        Ws[lc + 2][lr] = wv.z; Ws[lc + 3][lr] = wv.w;
        __syncthreads();
        #pragma unroll
        for (int kk = 0; kk < 16; kk++) {
            float a[4], wq[4];
            #pragma unroll
            for (int i = 0; i < 4; i++) a[i] = As[kk][ty * 4 + i];
            #pragma unroll
            for (int j = 0; j < 4; j++) wq[j] = Ws[kk][tx * 4 + j];
            #pragma unroll
            for (int i = 0; i < 4; i++)
                #pragma unroll
                for (int j = 0; j < 4; j++) c[i][j] += a[i] * wq[j];
        }
        __syncthreads();
    }
    #pragma unroll
    for (int i = 0; i < 4; i++) {
        int m = m0 + ty * 4 + i;
        #pragma unroll
        for (int j = 0; j < 4; j++) {
            int n = n0 + tx * 4 + j;
            if (n < N) {
                float v = c[i][j] + bias[n];
                if (RELU) v = fmaxf(v, 0.f);
                C[(size_t)m * N + n] = v;
            }
        }
    }
}

// ======================================================================
// TF32 tensor-core GEMM (decoder fc4): C = relu(A @ W^T + bias)
// BM=128, BN=64, BK=16; 256 threads (8 warps 4x2); warp tile 32x32.
// Requires M%128==0, K%16==0; N guarded.
// ======================================================================
__global__ void __launch_bounds__(256) gemm_tc(
        const float* __restrict__ A,
        const float* __restrict__ W,
        const float* __restrict__ bias,
        float* __restrict__ C,
        int M, int N, int K) {
    __shared__ float As[128][17];
    __shared__ float Ws[64][17];
    int t = threadIdx.x, lane = t & 31, w = t >> 5;
    int grp = lane >> 2, tig = lane & 3;
    int m0 = blockIdx.x * 128, n0 = blockIdx.y * 64;
    int mw = (w & 3) * 32, nw = (w >> 2) * 32;
    float acc[2][4][4];
    #pragma unroll
    for (int mi = 0; mi < 2; mi++)
        #pragma unroll
        for (int ni = 0; ni < 4; ni++)
            #pragma unroll
            for (int c = 0; c < 4; c++) acc[mi][ni][c] = 0.f;

    for (int k0 = 0; k0 < K; k0 += 16) {
        int ar = t >> 1, ak = (t & 1) * 8;
        const float* ap = A + (size_t)(m0 + ar) * K + k0 + ak;
        float4 v0 = *(const float4*)ap;
        float4 v1 = *(const float4*)(ap + 4);
        As[ar][ak + 0] = to_tf32(v0.x); As[ar][ak + 1] = to_tf32(v0.y);
        As[ar][ak + 2] = to_tf32(v0.z); As[ar][ak + 3] = to_tf32(v0.w);
        As[ar][ak + 4] = to_tf32(v1.x); As[ar][ak + 5] = to_tf32(v1.y);
        As[ar][ak + 6] = to_tf32(v1.z); As[ar][ak + 7] = to_tf32(v1.w);
        int wr = t >> 2, wk = (t & 3) * 4;
        float4 wv = make_float4(0.f, 0.f, 0.f, 0.f);
        if (n0 + wr < N)
            wv = *(const float4*)(W + (size_t)(n0 + wr) * K + k0 + wk);
        Ws[wr][wk + 0] = to_tf32(wv.x); Ws[wr][wk + 1] = to_tf32(wv.y);
        Ws[wr][wk + 2] = to_tf32(wv.z); Ws[wr][wk + 3] = to_tf32(wv.w);
        __syncthreads();
        #pragma unroll
        for (int kk = 0; kk < 2; kk++) {
            int kb = kk * 8;
            unsigned a[2][4];
            #pragma unroll
            for (int mi = 0; mi < 2; mi++) {
                int r = mw + mi * 16 + grp;
                a[mi][0] = __float_as_uint(As[r][kb + tig]);
                a[mi][1] = __float_as_uint(As[r + 8][kb + tig]);
                a[mi][2] = __float_as_uint(As[r][kb + tig + 4]);
                a[mi][3] = __float_as_uint(As[r + 8][kb + tig + 4]);
            }
            #pragma unroll
            for (int ni = 0; ni < 4; ni++) {
                int n = nw + ni * 8 + grp;
                unsigned bb0 = __float_as_uint(Ws[n][kb + tig]);
                unsigned bb1 = __float_as_uint(Ws[n][kb + tig + 4]);
                mma_tf32(acc[0][ni], a[0], bb0, bb1);
                mma_tf32(acc[1][ni], a[1], bb0, bb1);
            }
        }
        __syncthreads();
    }
    #pragma unroll
    for (int mi = 0; mi < 2; mi++) {
        #pragma unroll
        for (int ni = 0; ni < 4; ni++) {
            #pragma unroll
            for (int ci = 0; ci < 4; ci++) {
                int r = m0 + mw + mi * 16 + grp + ((ci >= 2) ? 8 : 0);
                int n = n0 + nw + ni * 8 + tig * 2 + (ci & 1);
                if (n < N)
                    C[(size_t)r * N + n] = fmaxf(acc[mi][ni][ci] + bias[n], 0.f);
            }
        }
    }
}

// ======================================================================
// fc2: z[B,32] = A[B,224] @ w[32,224]^T + b                    [round-1]
// ======================================================================
__global__ void fc2_kernel(const float* __restrict__ A,
                           const float* __restrict__ w,
                           const float* __restrict__ bias,
                           float* __restrict__ out) {
    __shared__ float ws[32 * 224];
    int t = threadIdx.x;
    for (int i = t; i < 7168; i += 256) ws[i] = w[i];
    __syncthreads();
    int n = t & 31, r = t >> 5;
    int b = blockIdx.x * 8 + r;
    const float* ap = A + (size_t)b * 224;
    const float* wp = ws + n * 224;
    float acc = bias[n];
    #pragma unroll 8
    for (int k = 0; k < 224; k++) acc += ap[k] * wp[k];
    out[(size_t)b * 32 + n] = acc;
}

// ======================================================================
// VQ helpers                                                  [round-1]
// ======================================================================
__global__ void enorm_kernel(const float* __restrict__ emb, float* __restrict__ enorm) {
    int e = blockIdx.x * blockDim.x + threadIdx.x;
    if (e < NE) {
        float s = 0.f;
        #pragma unroll
        for (int d = 0; d < ZD; d++) { float v = emb[e * ZD + d]; s += v * v; }
        enorm[e] = s;
    }
}

__global__ void zero_kernel(float* __restrict__ counts, float* __restrict__ sums,
                            float* __restrict__ loss) {
    int i = blockIdx.x * blockDim.x + threadIdx.x;
    if (i < NE) counts[i] = 0.f;
    if (i < NE * ZD) sums[i] = 0.f;
    if (i == 0) loss[0] = 0.f;
}

__global__ void vq_kernel(const float* __restrict__ z,
                          const float* __restrict__ emb,
                          const float* __restrict__ enorm,
                          int* __restrict__ idx,
                          float* __restrict__ counts,
                          float* __restrict__ sums,
                          float* __restrict__ loss) {
    int gw = (blockIdx.x * blockDim.x + threadIdx.x) >> 5;
    int lane = threadIdx.x & 31;
    int wl = threadIdx.x >> 5;
    __shared__ float zs[8][ZD];
    if (gw >= BATCH) return;
    zs[wl][lane] = z[(size_t)gw * ZD + lane];
    __syncwarp();
    float best = 3.4e38f; int bi = NE;
    for (int e = lane; e < NE; e += 32) {
        const float* ep = emb + e * ZD;
        float dot = 0.f;
        #pragma unroll
        for (int d = 0; d < ZD; d++) dot += zs[wl][d] * __ldg(ep + d);
        float s = enorm[e] - 2.f * dot;
        if (s < best) { best = s; bi = e; }
    }
    #pragma unroll
    for (int off = 16; off; off >>= 1) {
        float ob = __shfl_xor_sync(0xffffffffu, best, off);
        int   oi = __shfl_xor_sync(0xffffffffu, bi, off);
        if (ob < best || (ob == best && oi < bi)) { best = ob; bi = oi; }
    }
    float zl = zs[wl][lane];
    float diff = __ldg(emb + (size_t)bi * ZD + lane) - zl;
    float d2 = diff * diff;
    #pragma unroll
    for (int off = 16; off; off >>= 1) d2 += __shfl_xor_sync(0xffffffffu, d2, off);
    if (lane == 0) {
        idx[gw] = bi;
        atomicAdd(&counts[bi], 1.f);
        atomicAdd(loss, d2);
    }
    atomicAdd(&sums[bi * ZD + lane], zl);
}

__global__ void embnew_kernel(const float* __restrict__ m_mat,
                              const float* __restrict__ n_mat,
                              const float* __restrict__ sums,
                              const float* __restrict__ counts,
                              float* __restrict__ out) {
    int i = blockIdx.x * blockDim.x + threadIdx.x;
    if (i < NE * ZD) {
        int e = i >> 5;
        float m = m_mat[i] * GAMMA + sums[i] * ONE_M_GAMMA;
        float n = n_mat[e] * GAMMA + counts[e] * ONE_M_GAMMA;
        out[i] = m / n;
    }
}

__global__ void finalize_kernel(const float* __restrict__ counts,
                                const float* __restrict__ loss,
                                float* __restrict__ out_scalars) {
    __shared__ float red[NE];
    int t = threadIdx.x;
    float c = counts[t];
    float em = c * (1.f / (float)BATCH);
    red[t] = em * logf(em + 1e-10f);
    __syncthreads();
    for (int s = 256; s; s >>= 1) {
        if (t < s) red[t] += red[t + s];
        __syncthreads();
    }
    if (t == 0) {
        float q = loss[0] * (1.f / ((float)BATCH * (float)ZD));
        out_scalars[0] = q;
        out_scalars[1] = BETA * q;
        out_scalars[2] = expf(-red[0]);
    }
}

// ======================================================================
// fc3                                                          [round-1]
// ======================================================================
__global__ void fc3_kernel(const float* __restrict__ emb,
                           const int* __restrict__ idx,
                           const float* __restrict__ w,
                           const float* __restrict__ bias,
                           float* __restrict__ out) {
    __shared__ float zq[ZD];
    int b = blockIdx.x, t = threadIdx.x;
    if (t < ZD) zq[t] = emb[(size_t)idx[b] * ZD + t];
    __syncthreads();
    const float* wp = w + t * ZD;
    float acc = bias[t];
    #pragma unroll
    for (int k = 0; k < ZD; k++) acc += zq[k] * __ldg(wp + k);
    out[(size_t)b * 224 + t] = fmaxf(acc, 0.f);
}

// ======================================================================
// convt1: in[B,32,7,7] -> relu -> out[B,16,14,14]              [round-1]
// ======================================================================
__global__ void convt1_kernel(const float* __restrict__ in,
                              const float* __restrict__ w,
                              const float* __restrict__ bias,
                              float* __restrict__ out) {
    __shared__ float img[1568];
    int b = blockIdx.x, t = threadIdx.x;   // 224
    const float* ip = in + (size_t)b * 1568;
    for (int i = t; i < 1568; i += 224) img[i] = ip[i];
    __syncthreads();
    int oc = t / 14, oy = t % 14;
    float acc[14];
    float bv = bias[oc];
    #pragma unroll
    for (int j = 0; j < 14; j++) acc[j] = bv;
    for (int ic = 0; ic < 32; ic++) {
        const float* xc = img + ic * 49;
        const float* wp = w + ic * 256 + oc * 16;
        #pragma unroll
        for (int ky = 0; ky < 4; ky++) {
            int ty = oy + 1 - ky;
            if (ty < 0 || (ty & 1)) continue;
            int iy = ty >> 1;
            if (iy >= 7) continue;
            float row[7];
            #pragma unroll
            for (int j = 0; j < 7; j++) row[j] = xc[iy * 7 + j];
            #pragma unroll
            for (int kx = 0; kx < 4; kx++) {
                float wv = __ldg(wp + ky * 4 + kx);
                #pragma unroll
                for (int ox = 0; ox < 14; ox++) {
                    int txx = ox + 1 - kx;
                    if (txx >= 0 && !(txx & 1) && (txx >> 1) < 7)
                        acc[ox] += row[txx >> 1] * wv;
                }
            }
        }
    }
    float* op = out + (size_t)b * 3136 + oc * 196 + oy * 14;
    #pragma unroll
    for (int ox = 0; ox < 14; ox++) op[ox] = fmaxf(acc[ox], 0.f);
}

// ======================================================================
// convt2: in[B,16,14,14] -> out[B,1,28,28]                     [round-1]
// ======================================================================
__global__ void convt2_kernel(const float* __restrict__ in,
                              const float* __restrict__ w,
                              const float* __restrict__ bias,
                              float* __restrict__ out) {
    __shared__ float img[3136];
    __shared__ float ws[256];
    int b = blockIdx.x, t = threadIdx.x;   // 256
    const float* ip = in + (size_t)b * 3136;
    for (int i = t; i < 3136; i += 256) img[i] = ip[i];
    if (t < 256) ws[t] = w[t];
    __syncthreads();
    float bv = bias[0];
    float* op = out + (size_t)b * 784;
    for (int o = t; o < 784; o += 256) {
        int oy = o / 28, ox = o % 28;
        float acc = bv;
        #pragma unroll
        for (int ky = 0; ky < 4; ky++) {
            int ty = oy + 1 - ky;
            if (ty < 0 || (ty & 1)) continue;
            int iy = ty >> 1;
            if (iy >= 14) continue;
            #pragma unroll
            for (int kx = 0; kx < 4; kx++) {
                int tx = ox + 1 - kx;
                if (tx < 0 || (tx & 1)) continue;
                int ix = tx >> 1;
                if (ix >= 14) continue;
                #pragma unroll
                for (int ic = 0; ic < 16; ic++)
                    acc += img[ic * 196 + iy * 14 + ix] * ws[ic * 16 + ky * 4 + kx];
            }
        }
        op[o] = acc;
    }
}

// ======================================================================
// launch
// ======================================================================
extern "C" void kernel_launch(void* const* d_in, const int* in_sizes, int n_in,
                              void* d_out, int out_size) {
    const float* x        = (const float*)d_in[0];
    const float* conv1_w  = (const float*)d_in[1];
    const float* conv1_b  = (const float*)d_in[2];
    const float* conv2_w  = (const float*)d_in[3];
    const float* conv2_b  = (const float*)d_in[4];
    const float* res1_w1  = (const float*)d_in[5];
    const float* res1_w2  = (const float*)d_in[6];
    const float* fc1_w    = (const float*)d_in[7];
    const float* fc1_b    = (const float*)d_in[8];
    const float* fc2_w    = (const float*)d_in[9];
    const float* fc2_b    = (const float*)d_in[10];
    const float* emb      = (const float*)d_in[11];
    const float* n_mat    = (const float*)d_in[12];
    const float* m_mat    = (const float*)d_in[13];
    const float* fc3_w    = (const float*)d_in[14];
    const float* fc3_b    = (const float*)d_in[15];
    const float* fc4_w    = (const float*)d_in[16];
    const float* fc4_b    = (const float*)d_in[17];
    const float* res2_w1  = (const float*)d_in[18];
    const float* res2_w2  = (const float*)d_in[19];
    const float* convt1_w = (const float*)d_in[20];
    const float* convt1_b = (const float*)d_in[21];
    const float* convt2_w = (const float*)d_in[22];
    const float* convt2_b = (const float*)d_in[23];
    float* out = (float*)d_out;

    float *h1, *h2, *a, *z, *enorm, *counts, *sums, *loss;
    int* idx;
    cudaGetSymbolAddress((void**)&h1,     g_h1);
    cudaGetSymbolAddress((void**)&h2,     g_h2);
    cudaGetSymbolAddress((void**)&a,      g_a);
    cudaGetSymbolAddress((void**)&z,      g_z);
    cudaGetSymbolAddress((void**)&idx,    g_idx);
    cudaGetSymbolAddress((void**)&enorm,  g_enorm);
    cudaGetSymbolAddress((void**)&counts, g_counts);
    cudaGetSymbolAddress((void**)&sums,   g_sums);
    cudaGetSymbolAddress((void**)&loss,   g_loss);

    cudaFuncSetAttribute(res_tc_kernel,
                         cudaFuncAttributeMaxDynamicSharedMemorySize, RTC_SMEMB);

    // encoder (exact fp32 — VQ path bit-identical to round 1)
    conv1_kernel<<<BATCH, 256>>>(x, conv1_w, conv1_b, h1);
    conv2_kernel<<<BATCH, 224>>>(h1, conv2_w, conv2_b, h2);
    res_kernel  <<<BATCH, 448>>>(h2, res1_w1, res1_w2);
    gemm_nt<1><<<dim3(BATCH / 64, (224 + 63) / 64), 256>>>(h2, fc1_w, fc1_b, a,
                                                           BATCH, 224, 1568);
    fc2_kernel<<<BATCH / 8, 256>>>(a, fc2_w, fc2_b, z);

    // VQ
    zero_kernel <<<(NE * ZD + 255) / 256, 256>>>(counts, sums, loss);
    enorm_kernel<<<2, 256>>>(emb, enorm);
    vq_kernel   <<<BATCH / 8, 256>>>(z, emb, enorm, idx, counts, sums, loss);
    embnew_kernel  <<<(NE * ZD + 255) / 256, 256>>>(m_mat, n_mat, sums, counts,
                                                    out + OFF_SCAL + 3);
    finalize_kernel<<<1, NE>>>(counts, loss, out + OFF_SCAL);

    // decoder (tf32 tensor cores for fc4 + res2)
    fc3_kernel<<<BATCH, 224>>>(emb, idx, fc3_w, fc3_b, a);
    gemm_tc<<<dim3(BATCH / 128, (1568 + 63) / 64), 256>>>(a, fc4_w, fc4_b, h2,
                                                          BATCH, 1568, 224);
    res_tc_kernel<<<BATCH / 4, 256, RTC_SMEMB>>>(h2, res2_w1, res2_w2);
    convt1_kernel<<<BATCH, 224>>>(h2, convt1_w, convt1_b, h1);
    convt2_kernel<<<BATCH, 256>>>(h1, convt2_w, convt2_b, out);
}

// round 4
// speedup vs baseline: 1.5211x; 1.2305x over previous
#include <cuda_runtime.h>
#include <cstdint>
#include <math.h>

// ---------------- problem constants ----------------
#define BATCH 16384
#define ZD 32
#define NE 512
#define GAMMA 0.99f
#define ONE_M_GAMMA 0.01f
#define BETA 1.0f

#define OFF_SCAL (BATCH * 784)   // x_rec size
// d_out layout: [x_rec (B*784)][quant][commit][perplexity][emb_new (512*32)]

// ---------------- scratch ----------------
__device__ float g_h1[BATCH * 16 * 14 * 14];
__device__ float g_h2[BATCH * 32 * 7 * 7];
__device__ float g_a [BATCH * 224];
__device__ float g_z [BATCH * ZD];
__device__ int   g_idx[BATCH];
__device__ float g_enorm[NE];
__device__ float g_counts[NE];
__device__ float g_sums[NE * ZD];
__device__ float g_loss[1];

// ---------------- tf32 mma helpers ----------------
__device__ __forceinline__ float to_tf32(float x) {
    float y;
    asm("cvt.rna.tf32.f32 %0, %1;" : "=f"(y) : "f"(x));
    return y;
}

__device__ __forceinline__ void split_tf32(float v, unsigned& hi, unsigned& lo) {
    float h;
    asm("cvt.rna.tf32.f32 %0, %1;" : "=f"(h) : "f"(v));
    float l = v - h;
    float l2;
    asm("cvt.rna.tf32.f32 %0, %1;" : "=f"(l2) : "f"(l));
    hi = __float_as_uint(h);
    lo = __float_as_uint(l2);
}

__device__ __forceinline__ void mma_tf32(float* d, const unsigned* a,
                                         unsigned b0, unsigned b1) {
    asm volatile(
        "mma.sync.aligned.m16n8k8.row.col.f32.tf32.tf32.f32 "
        "{%0,%1,%2,%3}, {%4,%5,%6,%7}, {%8,%9}, {%0,%1,%2,%3};\n"
        : "+f"(d[0]), "+f"(d[1]), "+f"(d[2]), "+f"(d[3])
        : "r"(a[0]), "r"(a[1]), "r"(a[2]), "r"(a[3]), "r"(b0), "r"(b1));
}

// 3-pass split mma: acc += a*b with ~fp32 accuracy
__device__ __forceinline__ void mma3(float* d, const unsigned* ah, const unsigned* al,
                                     unsigned bh0, unsigned bh1,
                                     unsigned bl0, unsigned bl1) {
    mma_tf32(d, ah, bl0, bl1);
    mma_tf32(d, al, bh0, bh1);
    mma_tf32(d, ah, bh0, bh1);
}

// ======================================================================
// conv1: x[B,1,28,28] -> relu -> h1[B,16,14,14]   (k4 s2 p1)  fp32
// ======================================================================
__global__ void conv1_kernel(const float* __restrict__ x,
                             const float* __restrict__ w,
                             const float* __restrict__ bias,
                             float* __restrict__ out) {
    __shared__ float img[784];
    __shared__ float ws[256];
    int b = blockIdx.x, t = threadIdx.x;
    const float* ip = x + (size_t)b * 784;
    for (int i = t; i < 784; i += 256) img[i] = ip[i];
    if (t < 256) ws[t] = w[t];
    __syncthreads();
    float* op = out + (size_t)b * 3136;
    for (int o = t; o < 3136; o += 256) {
        int oc = o / 196, s = o % 196, oy = s / 14, ox = s % 14;
        float acc = bias[oc];
        const float* wp = ws + oc * 16;
        #pragma unroll
        for (int ky = 0; ky < 4; ky++) {
            int iy = 2 * oy - 1 + ky;
            if ((unsigned)iy < 28u) {
                #pragma unroll
                for (int kx = 0; kx < 4; kx++) {
                    int ix = 2 * ox - 1 + kx;
                    if ((unsigned)ix < 28u)
                        acc += img[iy * 28 + ix] * wp[ky * 4 + kx];
                }
            }
        }
        op[o] = fmaxf(acc, 0.f);
    }
}

// ======================================================================
// conv2 3xTF32 shift-GEMM: h1[B,16,14,14] -> h2[B,32,7,7] (k4 s2 p1)
// 4 img/CTA, 256 thr (8 warps x 32 rows). Rows = (img, outpos<64).
// A base = padded coord (2py,2px); 16 tap shifts; K=16 ch per shift.
// ======================================================================
#define C2_IMSZ 4608                   // 256 pos * 18 pitch
#define C2_ZOFF (4 * C2_IMSZ)          // 18432 (5th block = zeros)
#define C2_XIN  (5 * C2_IMSZ)          // 23040
#define C2_WOFF C2_XIN
#define C2_WSZ  (16 * 16 * 36)         // 9216
#define C2_SMEM ((C2_XIN + C2_WSZ) * 4)  // 129024 B

__global__ void __launch_bounds__(256) conv2_tc3(
        const float* __restrict__ in,
        const float* __restrict__ w,
        const float* __restrict__ bias,
        float* __restrict__ out) {
    extern __shared__ float sm[];
    float* xin = sm;
    float* wt  = sm + C2_WOFF;
    int t = threadIdx.x;
    int b0 = blockIdx.x * 4;

    for (int i = t; i < C2_XIN; i += 256) xin[i] = 0.f;
    __syncthreads();
    for (int i = t; i < 4 * 3136; i += 256) {
        int img = i / 3136, j = i % 3136;
        int ic = j / 196, p = j % 196, iy = p / 14, ix = p % 14;
        xin[img * C2_IMSZ + ((iy + 1) * 16 + (ix + 1)) * 18 + ic] =
            in[(size_t)(b0 + img) * 3136 + j];
    }
    for (int i = t; i < 8192; i += 256) {           // [oc][ic][s] -> [s][ic][oc]
        int oc = i / 256, r = i % 256, ic = r / 16, s = r % 16;
        wt[s * 576 + ic * 36 + oc] = w[i];
    }
    __syncthreads();

    int lane = t & 31, wrp = t >> 5;
    int grp = lane >> 2, tig = lane & 3;
    int wm = wrp * 32;

    int rb[2][2];
    #pragma unroll
    for (int mi = 0; mi < 2; mi++)
        #pragma unroll
        for (int h = 0; h < 2; h++) {
            int r = wm + mi * 16 + grp + h * 8;
            int img = r >> 6, p = r & 63;
            rb[mi][h] = (p < 49)
                ? img * C2_IMSZ + ((p / 7) * 32 + (p % 7) * 2) * 18
                : C2_ZOFF;
        }

    float acc[2][4][4];
    #pragma unroll
    for (int mi = 0; mi < 2; mi++)
        #pragma unroll
        for (int ni = 0; ni < 4; ni++)
            #pragma unroll
            for (int c = 0; c < 4; c++) acc[mi][ni][c] = 0.f;

    #pragma unroll
    for (int ky = 0; ky < 4; ky++) {
        #pragma unroll
        for (int kx = 0; kx < 4; kx++) {
            int soff = (ky * 16 + kx) * 18;
            const float* ws = wt + (ky * 4 + kx) * 576;
            #pragma unroll
            for (int kk = 0; kk < 2; kk++) {
                int kb = kk * 8;
                unsigned ah[2][4], al[2][4];
                #pragma unroll
                for (int mi = 0; mi < 2; mi++) {
                    split_tf32(xin[rb[mi][0] + soff + kb + tig],     ah[mi][0], al[mi][0]);
                    split_tf32(xin[rb[mi][1] + soff + kb + tig],     ah[mi][1], al[mi][1]);
                    split_tf32(xin[rb[mi][0] + soff + kb + tig + 4], ah[mi][2], al[mi][2]);
                    split_tf32(xin[rb[mi][1] + soff + kb + tig + 4], ah[mi][3], al[mi][3]);
                }
                #pragma unroll
                for (int ni = 0; ni < 4; ni++) {
                    unsigned bh0, bl0, bh1, bl1;
                    split_tf32(ws[(kb + tig) * 36 + ni * 8 + grp],     bh0, bl0);
                    split_tf32(ws[(kb + tig + 4) * 36 + ni * 8 + grp], bh1, bl1);
                    mma3(acc[0][ni], ah[0], al[0], bh0, bh1, bl0, bl1);
                    mma3(acc[1][ni], ah[1], al[1], bh0, bh1, bl0, bl1);
                }
            }
        }
    }

    #pragma unroll
    for (int mi = 0; mi < 2; mi++) {
        #pragma unroll
        for (int ni = 0; ni < 4; ni++) {
            #pragma unroll
            for (int ci = 0; ci < 4; ci++) {
                int r = wm + mi * 16 + grp + ((ci >= 2) ? 8 : 0);
                int img = r >> 6, p = r & 63;
                if (p < 49) {
                    int oc = ni * 8 + tig * 2 + (ci & 1);
                    out[(size_t)(b0 + img) * 1568 + oc * 49 + p] =
                        acc[mi][ni][ci] + __ldg(bias + oc);
                }
            }
        }
    }
}

// ======================================================================
// res stack 3xTF32 (encoder): y = relu(x + w2*relu(w1*relu(x)))
// 4 img/CTA, 256 thr. smem stores raw fp32; split at fragment load.
// ======================================================================
#define R3_IMSZ  2916                    // 81 * 36
#define R3_ZOFF  (4 * R3_IMSZ)           // 11664
#define R3_XIN   (R3_ZOFF + 768)         // 12432
#define R3_W1OFF R3_XIN
#define R3_W1SZ  (9 * 32 * 68)           // 19584
#define R3_W2OFF (R3_W1OFF + R3_W1SZ)
#define R3_W2SZ  (64 * 36)               // 2304
#define R3_RSOFF (R3_W2OFF + R3_W2SZ)
#define R3_RSSZ  (256 * 68)              // 17408
#define R3_SMEM  ((R3_RSOFF + R3_RSSZ) * 4)   // 206912 B

__global__ void __launch_bounds__(256) res_tc3(
        float* __restrict__ buf,
        const float* __restrict__ pw1,
        const float* __restrict__ pw2) {
    extern __shared__ float sm[];
    float* xin = sm;
    float* w1s = sm + R3_W1OFF;
    float* w2s = sm + R3_W2OFF;
    float* rs  = sm + R3_RSOFF;
    int t = threadIdx.x;
    int b0 = blockIdx.x * 4;

    for (int i = t; i < R3_XIN; i += 256) xin[i] = 0.f;
    __syncthreads();
    for (int i = t; i < 64 * 32 * 9; i += 256) {
        int oc = i / 288, rr = i % 288, ic = rr / 9, s = rr % 9;
        w1s[s * 2176 + ic * 68 + oc] = pw1[i];
    }
    for (int i = t; i < 2048; i += 256) {
        int oc = i >> 6, ic = i & 63;
        w2s[ic * 36 + oc] = pw2[i];
    }
    for (int i = t; i < 4 * 1568; i += 256) {
        int img = i / 1568, j = i % 1568;
        int ch = j / 49, p = j % 49, py = p / 7, px = p % 7;
        float v = buf[(size_t)(b0 + img) * 1568 + j];
        xin[img * R3_IMSZ + ((py + 1) * 9 + (px + 1)) * 36 + ch] = fmaxf(v, 0.f);
    }
    __syncthreads();

    int lane = t & 31, wrp = t >> 5;
    int grp = lane >> 2, tig = lane & 3;
    int wm = wrp * 32;

    int rb[2][2];
    #pragma unroll
    for (int mi = 0; mi < 2; mi++)
        #pragma unroll
        for (int h = 0; h < 2; h++) {
            int r = wm + mi * 16 + grp + h * 8;
            int img = r >> 6, p = r & 63;
            rb[mi][h] = (p < 49)
                ? img * R3_IMSZ + ((p / 7) * 9 + (p % 7)) * 36
                : R3_ZOFF;
        }

    // ---- phase 1: conv3x3 (32->64), 3xTF32 ----
    float acc[2][8][4];
    #pragma unroll
    for (int mi = 0; mi < 2; mi++)
        #pragma unroll
        for (int ni = 0; ni < 8; ni++)
            #pragma unroll
            for (int c = 0; c < 4; c++) acc[mi][ni][c] = 0.f;

    #pragma unroll
    for (int ky = 0; ky < 3; ky++) {
        #pragma unroll
        for (int kx = 0; kx < 3; kx++) {
            int soff = (ky * 9 + kx) * 36;
            const float* wb = w1s + (ky * 3 + kx) * 2176;
            #pragma unroll
            for (int kk = 0; kk < 4; kk++) {
                int kb = kk * 8;
                unsigned ah[2][4], al[2][4];
                #pragma unroll
                for (int mi = 0; mi < 2; mi++) {
                    split_tf32(xin[rb[mi][0] + soff + kb + tig],     ah[mi][0], al[mi][0]);
                    split_tf32(xin[rb[mi][1] + soff + kb + tig],     ah[mi][1], al[mi][1]);
                    split_tf32(xin[rb[mi][0] + soff + kb + tig + 4], ah[mi][2], al[mi][2]);
                    split_tf32(xin[rb[mi][1] + soff + kb + tig + 4], ah[mi][3], al[mi][3]);
                }
                #pragma unroll
                for (int ni = 0; ni < 8; ni++) {
                    unsigned bh0, bl0, bh1, bl1;
                    split_tf32(wb[(kb + tig) * 68 + ni * 8 + grp],     bh0, bl0);
                    split_tf32(wb[(kb + tig + 4) * 68 + ni * 8 + grp], bh1, bl1);
                    mma3(acc[0][ni], ah[0], al[0], bh0, bh1, bl0, bl1);
                    mma3(acc[1][ni], ah[1], al[1], bh0, bh1, bl0, bl1);
                }
            }
        }
    }

    // relu -> rs (raw fp32, pitch 68); warp-private rows
    #pragma unroll
    for (int mi = 0; mi < 2; mi++) {
        int rlo = wm + mi * 16 + grp, rhi = rlo + 8;
        #pragma unroll
        for (int ni = 0; ni < 8; ni++) {
            int c0 = ni * 8 + tig * 2;
            rs[rlo * 68 + c0]     = fmaxf(acc[mi][ni][0], 0.f);
            rs[rlo * 68 + c0 + 1] = fmaxf(acc[mi][ni][1], 0.f);
            rs[rhi * 68 + c0]     = fmaxf(acc[mi][ni][2], 0.f);
            rs[rhi * 68 + c0 + 1] = fmaxf(acc[mi][ni][3], 0.f);
        }
    }
    __syncwarp();

    // ---- phase 2: conv1x1 (64->32), 3xTF32 ----
    float acc2[2][4][4];
    #pragma unroll
    for (int mi = 0; mi < 2; mi++)
        #pragma unroll
        for (int ni = 0; ni < 4; ni++)
            #pragma unroll
            for (int c = 0; c < 4; c++) acc2[mi][ni][c] = 0.f;

    #pragma unroll
    for (int kk = 0; kk < 8; kk++) {
        int kb = kk * 8;
        unsigned ah[2][4], al[2][4];
        #pragma unroll
        for (int mi = 0; mi < 2; mi++) {
            int rlo = wm + mi * 16 + grp;
            split_tf32(rs[rlo * 68 + kb + tig],           ah[mi][0], al[mi][0]);
            split_tf32(rs[(rlo + 8) * 68 + kb + tig],     ah[mi][1], al[mi][1]);
            split_tf32(rs[rlo * 68 + kb + tig + 4],       ah[mi][2], al[mi][2]);
            split_tf32(rs[(rlo + 8) * 68 + kb + tig + 4], ah[mi][3], al[mi][3]);
        }
        #pragma unroll
        for (int ni = 0; ni < 4; ni++) {
            unsigned bh0, bl0, bh1, bl1;
            split_tf32(w2s[(kb + tig) * 36 + ni * 8 + grp],     bh0, bl0);
            split_tf32(w2s[(kb + tig + 4) * 36 + ni * 8 + grp], bh1, bl1);
            mma3(acc2[0][ni], ah[0], al[0], bh0, bh1, bl0, bl1);
            mma3(acc2[1][ni], ah[1], al[1], bh0, bh1, bl0, bl1);
        }
    }

    // epilogue: +residual (exact), relu, store
    #pragma unroll
    for (int mi = 0; mi < 2; mi++) {
        int rlo = wm + mi * 16 + grp;
        #pragma unroll
        for (int ni = 0; ni < 4; ni++) {
            #pragma unroll
            for (int ci = 0; ci < 4; ci++) {
                int r = rlo + ((ci >= 2) ? 8 : 0);
                int img = r >> 6, p = r & 63;
                if (p < 49) {
                    int ch = ni * 8 + tig * 2 + (ci & 1);
                    size_t g = (size_t)(b0 + img) * 1568 + ch * 49 + p;
                    float v = acc2[mi][ni][ci] + __ldg(buf + g);
                    buf[g] = fmaxf(v, 0.f);
                }
            }
        }
    }
}

// ======================================================================
// res stack single-TF32 (decoder)  [round-3, proven]
// ======================================================================
#define RTC_IMSZ  2673
#define RTC_ZOFF  (4 * RTC_IMSZ)
#define RTC_XIN   (RTC_ZOFF + 704)
#define RTC_W1OFF RTC_XIN
#define RTC_W1SZ  (9 * 32 * 68)
#define RTC_W2OFF (RTC_W1OFF + RTC_W1SZ)
#define RTC_W2SZ  (64 * 33)
#define RTC_RSOFF (RTC_W2OFF + RTC_W2SZ)
#define RTC_RSSZ  (256 * 65)
#define RTC_SMEMB ((RTC_RSOFF + RTC_RSSZ) * 4)

__global__ void __launch_bounds__(256) res_tc_kernel(
        float* __restrict__ buf,
        const float* __restrict__ pw1,
        const float* __restrict__ pw2) {
    extern __shared__ float sm[];
    float* xin = sm;
    float* w1s = sm + RTC_W1OFF;
    float* w2s = sm + RTC_W2OFF;
    float* rs  = sm + RTC_RSOFF;
    int t = threadIdx.x;
    int b0 = blockIdx.x * 4;

    for (int i = t; i < RTC_XIN; i += 256) xin[i] = 0.f;
    for (int i = t; i < 64 * 32 * 9; i += 256) {
        int oc = i / 288, rr = i % 288, ic = rr / 9, s = rr % 9;
        w1s[s * 2176 + ic * 68 + oc] = to_tf32(pw1[i]);
    }
    for (int i = t; i < 2048; i += 256) {
        int oc = i >> 6, ic = i & 63;
        w2s[ic * 33 + oc] = to_tf32(pw2[i]);
    }
    __syncthreads();
    for (int i = t; i < 4 * 1568; i += 256) {
        int img = i / 1568, j = i % 1568;
        int ch = j / 49, p = j % 49, py = p / 7, px = p % 7;
        float v = buf[(size_t)(b0 + img) * 1568 + j];
        xin[img * RTC_IMSZ + ((py + 1) * 9 + (px + 1)) * 33 + ch] =
            to_tf32(fmaxf(v, 0.f));
    }
    __syncthreads();

    int lane = t & 31, w = t >> 5;
    int grp = lane >> 2, tig = lane & 3;
    int wm = w * 32;

    int rb[2][2];
    #pragma unroll
    for (int mi = 0; mi < 2; mi++)
        #pragma unroll
        for (int h = 0; h < 2; h++) {
            int r = wm + mi * 16 + grp + h * 8;
            int img = r >> 6, p = r & 63;
            rb[mi][h] = (p < 49)
                ? img * RTC_IMSZ + ((p / 7) * 9 + (p % 7)) * 33
                : RTC_ZOFF;
        }

    float acc[2][8][4];
    #pragma unroll
    for (int mi = 0; mi < 2; mi++)
        #pragma unroll
        for (int ni = 0; ni < 8; ni++)
            #pragma unroll
            for (int c = 0; c < 4; c++) acc[mi][ni][c] = 0.f;

    #pragma unroll
    for (int ky = 0; ky < 3; ky++) {
        #pragma unroll
        for (int kx = 0; kx < 3; kx++) {
            int soff = (ky * 9 + kx) * 33;
            const float* wb = w1s + (ky * 3 + kx) * 2176;
            #pragma unroll
            for (int kk = 0; kk < 4; kk++) {
                int kb = kk * 8;
                unsigned a[2][4];
                #pragma unroll
                for (int mi = 0; mi < 2; mi++) {
                    a[mi][0] = __float_as_uint(xin[rb[mi][0] + soff + kb + tig]);
                    a[mi][1] = __float_as_uint(xin[rb[mi][1] + soff + kb + tig]);
                    a[mi][2] = __float_as_uint(xin[rb[mi][0] + soff + kb + tig + 4]);
                    a[mi][3] = __float_as_uint(xin[rb[mi][1] + soff + kb + tig + 4]);
                }
                #pragma unroll
                for (int ni = 0; ni < 8; ni++) {
                    unsigned bb0 = __float_as_uint(wb[(kb + tig) * 68 + ni * 8 + grp]);
                    unsigned bb1 = __float_as_uint(wb[(kb + tig + 4) * 68 + ni * 8 + grp]);
                    mma_tf32(acc[0][ni], a[0], bb0, bb1);
                    mma_tf32(acc[1][ni], a[1], bb0, bb1);
                }
            }
        }
    }

    #pragma unroll
    for (int mi = 0; mi < 2; mi++) {
        int rlo = wm + mi * 16 + grp, rhi = rlo + 8;
        #pragma unroll
        for (int ni = 0; ni < 8; ni++) {
            int c0 = ni * 8 + tig * 2;
            rs[rlo * 65 + c0]     = to_tf32(fmaxf(acc[mi][ni][0], 0.f));
            rs[rlo * 65 + c0 + 1] = to_tf32(fmaxf(acc[mi][ni][1], 0.f));
            rs[rhi * 65 + c0]     = to_tf32(fmaxf(acc[mi][ni][2], 0.f));
            rs[rhi * 65 + c0 + 1] = to_tf32(fmaxf(acc[mi][ni][3], 0.f));
        }
    }
    __syncwarp();

    float acc2[2][4][4];
    #pragma unroll
    for (int mi = 0; mi < 2; mi++)
        #pragma unroll
        for (int ni = 0; ni < 4; ni++)
            #pragma unroll
            for (int c = 0; c < 4; c++) acc2[mi][ni][c] = 0.f;

    #pragma unroll
    for (int kk = 0; kk < 8; kk++) {
        int kb = kk * 8;
        unsigned a[2][4];
        #pragma unroll
        for (int mi = 0; mi < 2; mi++) {
            int rlo = wm + mi * 16 + grp;
            a[mi][0] = __float_as_uint(rs[rlo * 65 + kb + tig]);
            a[mi][1] = __float_as_uint(rs[(rlo + 8) * 65 + kb + tig]);
            a[mi][2] = __float_as_uint(rs[rlo * 65 + kb + tig + 4]);
            a[mi][3] = __float_as_uint(rs[(rlo + 8) * 65 + kb + tig + 4]);
        }
        #pragma unroll
        for (int ni = 0; ni < 4; ni++) {
            unsigned bb0 = __float_as_uint(w2s[(kb + tig) * 33 + ni * 8 + grp]);
            unsigned bb1 = __float_as_uint(w2s[(kb + tig + 4) * 33 + ni * 8 + grp]);
            mma_tf32(acc2[0][ni], a[0], bb0, bb1);
            mma_tf32(acc2[1][ni], a[1], bb0, bb1);
        }
    }

    #pragma unroll
    for (int mi = 0; mi < 2; mi++) {
        int rlo = wm + mi * 16 + grp;
        #pragma unroll
        for (int ni = 0; ni < 4; ni++) {
            #pragma unroll
            for (int ci = 0; ci < 4; ci++) {
                int r = rlo + ((ci >= 2) ? 8 : 0);
                int img = r >> 6, p = r & 63;
                if (p < 49) {
                    int ch = ni * 8 + tig * 2 + (ci & 1);
                    size_t g = (size_t)(b0 + img) * 1568 + ch * 49 + p;
                    float v = acc2[mi][ni][ci] + __ldg(buf + g);
                    buf[g] = fmaxf(v, 0.f);
                }
            }
        }
    }
}

// ======================================================================
// TF32 GEMM (single, decoder fc4): C = relu(A @ W^T + bias)
// BM=128 BN=64 BK=16, 256 thr                                 [round-3]
// ======================================================================
__global__ void __launch_bounds__(256) gemm_tc(
        const float* __restrict__ A,
        const float* __restrict__ W,
        const float* __restrict__ bias,
        float* __restrict__ C,
        int M, int N, int K) {
    __shared__ float As[128][17];
    __shared__ float Ws[64][17];
    int t = threadIdx.x, lane = t & 31, w = t >> 5;
    int grp = lane >> 2, tig = lane & 3;
    int m0 = blockIdx.x * 128, n0 = blockIdx.y * 64;
    int mw = (w & 3) * 32, nw = (w >> 2) * 32;
    float acc[2][4][4];
    #pragma unroll
    for (int mi = 0; mi < 2; mi++)
        #pragma unroll
        for (int ni = 0; ni < 4; ni++)
            #pragma unroll
            for (int c = 0; c < 4; c++) acc[mi][ni][c] = 0.f;

    for (int k0 = 0; k0 < K; k0 += 16) {
        int ar = t >> 1, ak = (t & 1) * 8;
        const float* ap = A + (size_t)(m0 + ar) * K + k0 + ak;
        float4 v0 = *(const float4*)ap;
        float4 v1 = *(const float4*)(ap + 4);
        As[ar][ak + 0] = to_tf32(v0.x); As[ar][ak + 1] = to_tf32(v0.y);
        As[ar][ak + 2] = to_tf32(v0.z); As[ar][ak + 3] = to_tf32(v0.w);
        As[ar][ak + 4] = to_tf32(v1.x); As[ar][ak + 5] = to_tf32(v1.y);
        As[ar][ak + 6] = to_tf32(v1.z); As[ar][ak + 7] = to_tf32(v1.w);
        int wr = t >> 2, wk = (t & 3) * 4;
        float4 wv = make_float4(0.f, 0.f, 0.f, 0.f);
        if (n0 + wr < N)
            wv = *(const float4*)(W + (size_t)(n0 + wr) * K + k0 + wk);
        Ws[wr][wk + 0] = to_tf32(wv.x); Ws[wr][wk + 1] = to_tf32(wv.y);
        Ws[wr][wk + 2] = to_tf32(wv.z); Ws[wr][wk + 3] = to_tf32(wv.w);
        __syncthreads();
        #pragma unroll
        for (int kk = 0; kk < 2; kk++) {
            int kb = kk * 8;
            unsigned a[2][4];
            #pragma unroll
            for (int mi = 0; mi < 2; mi++) {
                int r = mw + mi * 16 + grp;
                a[mi][0] = __float_as_uint(As[r][kb + tig]);
                a[mi][1] = __float_as_uint(As[r + 8][kb + tig]);
                a[mi][2] = __float_as_uint(As[r][kb + tig + 4]);
                a[mi][3] = __float_as_uint(As[r + 8][kb + tig + 4]);
            }
            #pragma unroll
            for (int ni = 0; ni < 4; ni++) {
                int n = nw + ni * 8 + grp;
                unsigned bb0 = __float_as_uint(Ws[n][kb + tig]);
                unsigned bb1 = __float_as_uint(Ws[n][kb + tig + 4]);
                mma_tf32(acc[0][ni], a[0], bb0, bb1);
                mma_tf32(acc[1][ni], a[1], bb0, bb1);
            }
        }
        __syncthreads();
    }
    #pragma unroll
    for (int mi = 0; mi < 2; mi++) {
        #pragma unroll
        for (int ni = 0; ni < 4; ni++) {
            #pragma unroll
            for (int ci = 0; ci < 4; ci++) {
                int r = m0 + mw + mi * 16 + grp + ((ci >= 2) ? 8 : 0);
                int n = n0 + nw + ni * 8 + tig * 2 + (ci & 1);
                if (n < N)
                    C[(size_t)r * N + n] = fmaxf(acc[mi][ni][ci] + bias[n], 0.f);
            }
        }
    }
}

// ======================================================================
// 3xTF32 GEMM (encoder fc1): C = relu(A @ W^T + bias), ~fp32 accurate
// ======================================================================
__global__ void __launch_bounds__(256) gemm_tc3(
        const float* __restrict__ A,
        const float* __restrict__ W,
        const float* __restrict__ bias,
        float* __restrict__ C,
        int M, int N, int K) {
    __shared__ float As[128][17];
    __shared__ float Ws[64][17];
    int t = threadIdx.x, lane = t & 31, w = t >> 5;
    int grp = lane >> 2, tig = lane & 3;
    int m0 = blockIdx.x * 128, n0 = blockIdx.y * 64;
    int mw = (w & 3) * 32, nw = (w >> 2) * 32;
    float acc[2][4][4];
    #pragma unroll
    for (int mi = 0; mi < 2; mi++)
        #pragma unroll
        for (int ni = 0; ni < 4; ni++)
            #pragma unroll
            for (int c = 0; c < 4; c++) acc[mi][ni][c] = 0.f;

    for (int k0 = 0; k0 < K; k0 += 16) {
        int ar = t >> 1, ak = (t & 1) * 8;
        const float* ap = A + (size_t)(m0 + ar) * K + k0 + ak;
        float4 v0 = *(const float4*)ap;
        float4 v1 = *(const float4*)(ap + 4);
        As[ar][ak + 0] = v0.x; As[ar][ak + 1] = v0.y;
        As[ar][ak + 2] = v0.z; As[ar][ak + 3] = v0.w;
        As[ar][ak + 4] = v1.x; As[ar][ak + 5] = v1.y;
        As[ar][ak + 6] = v1.z; As[ar][ak + 7] = v1.w;
        int wr = t >> 2, wk = (t & 3) * 4;
        float4 wv = make_float4(0.f, 0.f, 0.f, 0.f);
        if (n0 + wr < N)
            wv = *(const float4*)(W + (size_t)(n0 + wr) * K + k0 + wk);
        Ws[wr][wk + 0] = wv.x; Ws[wr][wk + 1] = wv.y;
        Ws[wr][wk + 2] = wv.z; Ws[wr][wk + 3] = wv.w;
        __syncthreads();
        #pragma unroll
        for (int kk = 0; kk < 2; kk++) {
            int kb = kk * 8;
            unsigned ah[2][4], al[2][4];
            #pragma unroll
            for (int mi = 0; mi < 2; mi++) {
                int r = mw + mi * 16 + grp;
                split_tf32(As[r][kb + tig],         ah[mi][0], al[mi][0]);
                split_tf32(As[r + 8][kb + tig],     ah[mi][1], al[mi][1]);
                split_tf32(As[r][kb + tig + 4],     ah[mi][2], al[mi][2]);
                split_tf32(As[r + 8][kb + tig + 4], ah[mi][3], al[mi][3]);
            }
            #pragma unroll
            for (int ni = 0; ni < 4; ni++) {
                int n = nw + ni * 8 + grp;
                unsigned bh0, bl0, bh1, bl1;
                split_tf32(Ws[n][kb + tig],     bh0, bl0);
                split_tf32(Ws[n][kb + tig + 4], bh1, bl1);
                mma3(acc[0][ni], ah[0], al[0], bh0, bh1, bl0, bl1);
                mma3(acc[1][ni], ah[1], al[1], bh0, bh1, bl0, bl1);
            }
        }
        __syncthreads();
    }
    #pragma unroll
    for (int mi = 0; mi < 2; mi++) {
        #pragma unroll
        for (int ni = 0; ni < 4; ni++) {
            #pragma unroll
            for (int ci = 0; ci < 4; ci++) {
                int r = m0 + mw + mi * 16 + grp + ((ci >= 2) ? 8 : 0);
                int n = n0 + nw + ni * 8 + tig * 2 + (ci & 1);
                if (n < N)
                    C[(size_t)r * N + n] = fmaxf(acc[mi][ni][ci] + bias[n], 0.f);
            }
        }
    }
}

// ======================================================================
// convt1 single-TF32 (decoder): in[B,32,7,7] -> relu -> out[B,16,14,14]
// 4 output phases (oy,ox parity); each phase = 2x2-shift GEMM.
// 2 img/CTA, 256 thr; warp w -> (img = w>>2, phase = w&3), 64 rows.
// ======================================================================
#define T1_IMSZ 2916                     // 81 * 36
#define T1_ZB   6240                     // zero base (soff in [-360,360])
#define T1_XIN  6664                     // 2*2916 + 832
#define T1_WOFF T1_XIN
#define T1_WSZ  (16 * 32 * 24)           // 12288
#define T1_SMEM ((T1_XIN + T1_WSZ) * 4)  // 75808 B

__global__ void __launch_bounds__(256) convt1_tc(
        const float* __restrict__ in,
        const float* __restrict__ w,
        const float* __restrict__ bias,
        float* __restrict__ out) {
    extern __shared__ float sm[];
    float* xin = sm;
    float* wt  = sm + T1_WOFF;
    int t = threadIdx.x;
    int b0 = blockIdx.x * 2;

    for (int i = t; i < T1_XIN; i += 256) xin[i] = 0.f;
    __syncthreads();
    for (int i = t; i < 2 * 1568; i += 256) {
        int img = i / 1568, j = i % 1568;
        int ic = j / 49, p = j % 49, iy = p / 7, ix = p % 7;
        xin[img * T1_IMSZ + ((iy + 1) * 9 + (ix + 1)) * 36 + ic] =
            to_tf32(in[(size_t)(b0 + img) * 1568 + j]);
    }
    for (int i = t; i < 32 * 256; i += 256) {    // w[ic][oc][ky][kx]
        int ic = i / 256, r = i % 256, oc = r / 16, s = r % 16;
        wt[s * 768 + ic * 24 + oc] = to_tf32(w[i]);
    }
    __syncthreads();

    int lane = t & 31, wrp = t >> 5;
    int grp = lane >> 2, tig = lane & 3;
    int img = wrp >> 2, ph = wrp & 3;
    int a = ph >> 1, bp = ph & 1;
    // phase tap tables: oy=2m+a uses (ky, dy) pairs
    int dyv[2], kyv[2], dxv[2], kxv[2];
    if (a == 0) { dyv[0] = 0; kyv[0] = 1; dyv[1] = -1; kyv[1] = 3; }
    else        { dyv[0] = 1; kyv[0] = 0; dyv[1] =  0; kyv[1] = 2; }
    if (bp == 0) { dxv[0] = 0; kxv[0] = 1; dxv[1] = -1; kxv[1] = 3; }
    else         { dxv[0] = 1; kxv[0] = 0; dxv[1] =  0; kxv[1] = 2; }

    int rb[4][2];
    #pragma unroll
    for (int mi = 0; mi < 4; mi++)
        #pragma unroll
        for (int h = 0; h < 2; h++) {
            int p = mi * 16 + grp + h * 8;
            rb[mi][h] = (p < 49)
                ? img * T1_IMSZ + ((p / 7 + 1) * 9 + (p % 7 + 1)) * 36
                : T1_ZB;
        }

    float acc[4][2][4];
    #pragma unroll
    for (int mi = 0; mi < 4; mi++)
        #pragma unroll
        for (int ni = 0; ni < 2; ni++)
            #pragma unroll
            for (int c = 0; c < 4; c++) acc[mi][ni][c] = 0.f;

    #pragma unroll
    for (int sy = 0; sy < 2; sy++) {
        #pragma unroll
        for (int sx = 0; sx < 2; sx++) {
            int soff = (dyv[sy] * 9 + dxv[sx]) * 36;
            const float* wsl = wt + (kyv[sy] * 4 + kxv[sx]) * 768;
            #pragma unroll
            for (int kk = 0; kk < 4; kk++) {
                int kb = kk * 8;
                unsigned afr[4][4];
                #pragma unroll
                for (int mi = 0; mi < 4; mi++) {
                    afr[mi][0] = __float_as_uint(xin[rb[mi][0] + soff + kb + tig]);
                    afr[mi][1] = __float_as_uint(xin[rb[mi][1] + soff + kb + tig]);
                    afr[mi][2] = __float_as_uint(xin[rb[mi][0] + soff + kb + tig + 4]);
                    afr[mi][3] = __float_as_uint(xin[rb[mi][1] + soff + kb + tig + 4]);
                }
                #pragma unroll
                for (int ni = 0; ni < 2; ni++) {
                    unsigned bb0 = __float_as_uint(wsl[(kb + tig) * 24 + ni * 8 + grp]);
                    unsigned bb1 = __float_as_uint(wsl[(kb + tig + 4) * 24 + ni * 8 + grp]);
                    #pragma unroll
                    for (int mi = 0; mi < 4; mi++)
                        mma_tf32(acc[mi][ni], afr[mi], bb0, bb1);
                }
            }
        }
    }

    #pragma unroll
    for (int mi = 0; mi < 4; mi++) {
        #pragma unroll
        for (int ni = 0; ni < 2; ni++) {
            #pragma unroll
            for (int ci = 0; ci < 4; ci++) {
                int p = mi * 16 + grp + ((ci >= 2) ? 8 : 0);
                if (p < 49) {
                    int m = p / 7, n = p % 7;
                    int oc = ni * 8 + tig * 2 + (ci & 1);
                    int oy = 2 * m + a, ox = 2 * n + bp;
                    float v = acc[mi][ni][ci] + __ldg(bias + oc);
                    out[(size_t)(b0 + img) * 3136 + oc * 196 + oy * 14 + ox] =
                        fmaxf(v, 0.f);
                }
            }
        }
    }
}

// ======================================================================
// fc2: z[B,32] = A[B,224] @ w^T + b  (fp32, feeds VQ)
// ======================================================================
__global__ void fc2_kernel(const float* __restrict__ A,
                           const float* __restrict__ w,
                           const float* __restrict__ bias,
                           float* __restrict__ out) {
    __shared__ float ws[32 * 224];
    int t = threadIdx.x;
    for (int i = t; i < 7168; i += 256) ws[i] = w[i];
    __syncthreads();
    int n = t & 31, r = t >> 5;
    int b = blockIdx.x * 8 + r;
    const float* ap = A + (size_t)b * 224;
    const float* wp = ws + n * 224;
    float acc = bias[n];
    #pragma unroll 8
    for (int k = 0; k < 224; k++) acc += ap[k] * wp[k];
    out[(size_t)b * 32 + n] = acc;
}

// ======================================================================
// VQ helpers (fp32 exact)
// ======================================================================
__global__ void enorm_kernel(const float* __restrict__ emb, float* __restrict__ enorm) {
    int e = blockIdx.x * blockDim.x + threadIdx.x;
    if (e < NE) {
        float s = 0.f;
        #pragma unroll
        for (int d = 0; d < ZD; d++) { float v = emb[e * ZD + d]; s += v * v; }
        enorm[e] = s;
    }
}

__global__ void zero_kernel(float* __restrict__ counts, float* __restrict__ sums,
                            float* __restrict__ loss) {
    int i = blockIdx.x * blockDim.x + threadIdx.x;
    if (i < NE) counts[i] = 0.f;
    if (i < NE * ZD) sums[i] = 0.f;
    if (i == 0) loss[0] = 0.f;
}

__global__ void vq_kernel(const float* __restrict__ z,
                          const float* __restrict__ emb,
                          const float* __restrict__ enorm,
                          int* __restrict__ idx,
                          float* __restrict__ counts,
                          float* __restrict__ sums,
                          float* __restrict__ loss) {
    int gw = (blockIdx.x * blockDim.x + threadIdx.x) >> 5;
    int lane = threadIdx.x & 31;
    int wl = threadIdx.x >> 5;
    __shared__ float zs[8][ZD];
    if (gw >= BATCH) return;
    zs[wl][lane] = z[(size_t)gw * ZD + lane];
    __syncwarp();
    float best = 3.4e38f; int bi = NE;
    for (int e = lane; e < NE; e += 32) {
        const float* ep = emb + e * ZD;
        float dot = 0.f;
        #pragma unroll
        for (int d = 0; d < ZD; d++) dot += zs[wl][d] * __ldg(ep + d);
        float s = enorm[e] - 2.f * dot;
        if (s < best) { best = s; bi = e; }
    }
    #pragma unroll
    for (int off = 16; off; off >>= 1) {
        float ob = __shfl_xor_sync(0xffffffffu, best, off);
        int   oi = __shfl_xor_sync(0xffffffffu, bi, off);
        if (ob < best || (ob == best && oi < bi)) { best = ob; bi = oi; }
    }
    float zl = zs[wl][lane];
    float diff = __ldg(emb + (size_t)bi * ZD + lane) - zl;
    float d2 = diff * diff;
    #pragma unroll
    for (int off = 16; off; off >>= 1) d2 += __shfl_xor_sync(0xffffffffu, d2, off);
    if (lane == 0) {
        idx[gw] = bi;
        atomicAdd(&counts[bi], 1.f);
        atomicAdd(loss, d2);
    }
    atomicAdd(&sums[bi * ZD + lane], zl);
}

__global__ void embnew_kernel(const float* __restrict__ m_mat,
                              const float* __restrict__ n_mat,
                              const float* __restrict__ sums,
                              const float* __restrict__ counts,
                              float* __restrict__ out) {
    int i = blockIdx.x * blockDim.x + threadIdx.x;
    if (i < NE * ZD) {
        int e = i >> 5;
        float m = m_mat[i] * GAMMA + sums[i] * ONE_M_GAMMA;
        float n = n_mat[e] * GAMMA + counts[e] * ONE_M_GAMMA;
        out[i] = m / n;
    }
}

__global__ void finalize_kernel(const float* __restrict__ counts,
                                const float* __restrict__ loss,
                                float* __restrict__ out_scalars) {
    __shared__ float red[NE];
    int t = threadIdx.x;
    float c = counts[t];
    float em = c * (1.f / (float)BATCH);
    red[t] = em * logf(em + 1e-10f);
    __syncthreads();
    for (int s = 256; s; s >>= 1) {
        if (t < s) red[t] += red[t + s];
        __syncthreads();
    }
    if (t == 0) {
        float q = loss[0] * (1.f / ((float)BATCH * (float)ZD));
        out_scalars[0] = q;
        out_scalars[1] = BETA * q;
        out_scalars[2] = expf(-red[0]);
    }
}

// ======================================================================
// fc3 (fp32)
// ======================================================================
__global__ void fc3_kernel(const float* __restrict__ emb,
                           const int* __restrict__ idx,
                           const float* __restrict__ w,
                           const float* __restrict__ bias,
                           float* __restrict__ out) {
    __shared__ float zq[ZD];
    int b = blockIdx.x, t = threadIdx.x;
    if (t < ZD) zq[t] = emb[(size_t)idx[b] * ZD + t];
    __syncthreads();
    const float* wp = w + t * ZD;
    float acc = bias[t];
    #pragma unroll
    for (int k = 0; k < ZD; k++) acc += zq[k] * __ldg(wp + k);
    out[(size_t)b * 224 + t] = fmaxf(acc, 0.f);
}

// ======================================================================
// convt2: in[B,16,14,14] -> out[B,1,28,28]  (fp32)
// ======================================================================
__global__ void convt2_kernel(const float* __restrict__ in,
                              const float* __restrict__ w,
                              const float* __restrict__ bias,
                              float* __restrict__ out) {
    __shared__ float img[3136];
    __shared__ float ws[256];
    int b = blockIdx.x, t = threadIdx.x;
    const float* ip = in + (size_t)b * 3136;
    for (int i = t; i < 3136; i += 256) img[i] = ip[i];
    if (t < 256) ws[t] = w[t];
    __syncthreads();
    float bv = bias[0];
    float* op = out + (size_t)b * 784;
    for (int o = t; o < 784; o += 256) {
        int oy = o / 28, ox = o % 28;
        float acc = bv;
        #pragma unroll
        for (int ky = 0; ky < 4; ky++) {
            int ty = oy + 1 - ky;
            if (ty < 0 || (ty & 1)) continue;
            int iy = ty >> 1;
            if (iy >= 14) continue;
            #pragma unroll
            for (int kx = 0; kx < 4; kx++) {
                int tx = ox + 1 - kx;
                if (tx < 0 || (tx & 1)) continue;
                int ix = tx >> 1;
                if (ix >= 14) continue;
                #pragma unroll
                for (int ic = 0; ic < 16; ic++)
                    acc += img[ic * 196 + iy * 14 + ix] * ws[ic * 16 + ky * 4 + kx];
            }
        }
        op[o] = acc;
    }
}

// ======================================================================
// launch
// ======================================================================
extern "C" void kernel_launch(void* const* d_in, const int* in_sizes, int n_in,
                              void* d_out, int out_size) {
    const float* x        = (const float*)d_in[0];
    const float* conv1_w  = (const float*)d_in[1];
    const float* conv1_b  = (const float*)d_in[2];
    const float* conv2_w  = (const float*)d_in[3];
    const float* conv2_b  = (const float*)d_in[4];
    const float* res1_w1  = (const float*)d_in[5];
    const float* res1_w2  = (const float*)d_in[6];
    const float* fc1_w    = (const float*)d_in[7];
    const float* fc1_b    = (const float*)d_in[8];
    const float* fc2_w    = (const float*)d_in[9];
    const float* fc2_b    = (const float*)d_in[10];
    const float* emb      = (const float*)d_in[11];
    const float* n_mat    = (const float*)d_in[12];
    const float* m_mat    = (const float*)d_in[13];
    const float* fc3_w    = (const float*)d_in[14];
    const float* fc3_b    = (const float*)d_in[15];
    const float* fc4_w    = (const float*)d_in[16];
    const float* fc4_b    = (const float*)d_in[17];
    const float* res2_w1  = (const float*)d_in[18];
    const float* res2_w2  = (const float*)d_in[19];
    const float* convt1_w = (const float*)d_in[20];
    const float* convt1_b = (const float*)d_in[21];
    const float* convt2_w = (const float*)d_in[22];
    const float* convt2_b = (const float*)d_in[23];
    float* out = (float*)d_out;

    float *h1, *h2, *a, *z, *enorm, *counts, *sums, *loss;
    int* idx;
    cudaGetSymbolAddress((void**)&h1,     g_h1);
    cudaGetSymbolAddress((void**)&h2,     g_h2);
    cudaGetSymbolAddress((void**)&a,      g_a);
    cudaGetSymbolAddress((void**)&z,      g_z);
    cudaGetSymbolAddress((void**)&idx,    g_idx);
    cudaGetSymbolAddress((void**)&enorm,  g_enorm);
    cudaGetSymbolAddress((void**)&counts, g_counts);
    cudaGetSymbolAddress((void**)&sums,   g_sums);
    cudaGetSymbolAddress((void**)&loss,   g_loss);

    cudaFuncSetAttribute(res_tc_kernel,
                         cudaFuncAttributeMaxDynamicSharedMemorySize, RTC_SMEMB);
    cudaFuncSetAttribute(res_tc3,
                         cudaFuncAttributeMaxDynamicSharedMemorySize, R3_SMEM);
    cudaFuncSetAttribute(conv2_tc3,
                         cudaFuncAttributeMaxDynamicSharedMemorySize, C2_SMEM);
    cudaFuncSetAttribute(convt1_tc,
                         cudaFuncAttributeMaxDynamicSharedMemorySize, T1_SMEM);

    // encoder (3xTF32 = fp32-class accuracy; VQ path preserved)
    conv1_kernel<<<BATCH, 256>>>(x, conv1_w, conv1_b, h1);
    conv2_tc3<<<BATCH / 4, 256, C2_SMEM>>>(h1, conv2_w, conv2_b, h2);
    res_tc3  <<<BATCH / 4, 256, R3_SMEM>>>(h2, res1_w1, res1_w2);
    gemm_tc3<<<dim3(BATCH / 128, 4), 256>>>(h2, fc1_w, fc1_b, a,
                                            BATCH, 224, 1568);
    fc2_kernel<<<BATCH / 8, 256>>>(a, fc2_w, fc2_b, z);

    // VQ
    zero_kernel <<<(NE * ZD + 255) / 256, 256>>>(counts, sums, loss);
    enorm_kernel<<<2, 256>>>(emb, enorm);
    vq_kernel   <<<BATCH / 8, 256>>>(z, emb, enorm, idx, counts, sums, loss);
    embnew_kernel  <<<(NE * ZD + 255) / 256, 256>>>(m_mat, n_mat, sums, counts,
                                                    out + OFF_SCAL + 3);
    finalize_kernel<<<1, NE>>>(counts, loss, out + OFF_SCAL);

    // decoder (single tf32)
    fc3_kernel<<<BATCH, 224>>>(emb, idx, fc3_w, fc3_b, a);
    gemm_tc<<<dim3(BATCH / 128, 25), 256>>>(a, fc4_w, fc4_b, h2,
                                            BATCH, 1568, 224);
    res_tc_kernel<<<BATCH / 4, 256, RTC_SMEMB>>>(h2, res2_w1, res2_w2);
    convt1_tc<<<BATCH / 2, 256, T1_SMEM>>>(h2, convt1_w, convt1_b, h1);
    convt2_kernel<<<BATCH, 256>>>(h1, convt2_w, convt2_b, out);
}